// round 12
// baseline (speedup 1.0000x reference)
#include <cuda_runtime.h>
#include <cuda_fp16.h>
#include <cstdint>
#include <cstddef>

// Problem constants
#define BB 16384
#define DD 256
#define LL 255
#define HH 8

// ---- device scratch ----
__device__ __align__(16) __half g_w1t[16 * 16 * 2048];
__device__ __align__(16) __half g_xh[128 * 4 * 8192];
__device__ __align__(16) __half g_h1[(size_t)LL * BB * HH];
__device__ __align__(16) float  g_mu[(size_t)LL * BB];
__device__ __align__(16) float  g_al[(size_t)LL * BB];

// ============================ helpers ============================
__device__ __forceinline__ uint32_t smem_u32(const void* p) {
    uint32_t a;
    asm("{ .reg .u64 t; cvta.to.shared.u64 t, %1; cvt.u32.u64 %0, t; }" : "=r"(a) : "l"(p));
    return a;
}
__device__ __forceinline__ unsigned long long pk2(float a, float b) {
    unsigned long long r;
    asm("mov.b64 %0, {%1, %2};" : "=l"(r) : "f"(a), "f"(b));
    return r;
}
__device__ __forceinline__ void fma2(unsigned long long& d, unsigned long long a, unsigned long long b) {
    asm("fma.rn.f32x2 %0, %1, %2, %0;" : "+l"(d) : "l"(a), "l"(b));
}
__device__ __forceinline__ float2 up2(unsigned long long v) {
    float2 r;
    asm("mov.b64 {%0, %1}, %2;" : "=f"(r.x), "=f"(r.y) : "l"(v));
    return r;
}
__device__ __forceinline__ float ftanha(float v) {
    float r;
    asm("tanh.approx.f32 %0, %1;" : "=f"(r) : "f"(v));
    return r;
}
__device__ __forceinline__ void ldsm4(uint32_t* r, uint32_t a) {
    asm volatile("ldmatrix.sync.aligned.m8n8.x4.shared.b16 {%0,%1,%2,%3}, [%4];"
                 : "=r"(r[0]), "=r"(r[1]), "=r"(r[2]), "=r"(r[3]) : "r"(a));
}
__device__ __forceinline__ void ldsm4t(uint32_t* r, uint32_t a) {
    asm volatile("ldmatrix.sync.aligned.m8n8.x4.trans.shared.b16 {%0,%1,%2,%3}, [%4];"
                 : "=r"(r[0]), "=r"(r[1]), "=r"(r[2]), "=r"(r[3]) : "r"(a));
}
__device__ __forceinline__ void mma_f16(float* d, const uint32_t* a, const uint32_t* b) {
    asm volatile("mma.sync.aligned.m16n8k16.row.col.f32.f16.f16.f32 "
                 "{%0,%1,%2,%3}, {%4,%5,%6,%7}, {%8,%9}, {%0,%1,%2,%3};"
                 : "+f"(d[0]), "+f"(d[1]), "+f"(d[2]), "+f"(d[3])
                 : "r"(a[0]), "r"(a[1]), "r"(a[2]), "r"(a[3]), "r"(b[0]), "r"(b[1]));
}
#define CP_ASYNC16(dst, src) \
    asm volatile("cp.async.cg.shared.global [%0], [%1], 16;" :: "r"(dst), "l"(src))
#define CP_COMMIT() asm volatile("cp.async.commit_group;" ::: "memory")
#define CP_WAIT1()  asm volatile("cp.async.wait_group 1;" ::: "memory")
#define CP_WAIT0()  asm volatile("cp.async.wait_group 0;" ::: "memory")

// ============== prep 1: W1 -> fp16 causal-masked swizzled tiles ==============
__global__ void __launch_bounds__(256) prep_w1(const float* __restrict__ W1) {
    const int nb = blockIdx.x, ks = blockIdx.y;
    __half* dst = g_w1t + (nb * 16 + ks) * 2048;
    #pragma unroll
    for (int i = 0; i < 8; ++i) {
        int e = threadIdx.x + i * 256;        // 0..2047 = 16k x 128n
        int k = e >> 7, nl = e & 127;
        int l = nb * 16 + (nl >> 3), h = nl & 7;
        int kg = ks * 16 + k;
        float v = (l < LL && kg <= l) ? W1[((size_t)l * DD + kg) * HH + h] : 0.f;
        uint32_t off = (uint32_t)k * 128 + ((((nl >> 3) ^ (k & 7))) << 3) + (nl & 7);
        dst[off] = __float2half(v);
    }
}

// ============== prep 2: x -> fp16 swizzled k-chunk tiles ==============
__global__ void __launch_bounds__(256) prep_x(const float* __restrict__ x) {
    int t = blockIdx.x * 256 + threadIdx.x;   // 524288 store-units of 16B
    int kg8 = t & 7;
    int r   = (t >> 3) & 127;
    int kbmb = t >> 10;
    int kb = kbmb & 3, mb = kbmb >> 2;
    const float* src = x + ((size_t)(mb * 128 + r) * DD + kb * 64 + kg8 * 8);
    float4 v0 = *(const float4*)src;
    float4 v1 = *(const float4*)(src + 4);
    __half2 h0 = __floats2half2_rn(v0.x, v0.y);
    __half2 h1 = __floats2half2_rn(v0.z, v0.w);
    __half2 h2 = __floats2half2_rn(v1.x, v1.y);
    __half2 h3 = __floats2half2_rn(v1.z, v1.w);
    uint4 pk = make_uint4(*(uint32_t*)&h0, *(uint32_t*)&h1, *(uint32_t*)&h2, *(uint32_t*)&h3);
    unsigned char* dp = (unsigned char*)g_xh + (size_t)(mb * 4 + kb) * 16384
                      + (uint32_t)r * 128 + (((uint32_t)(kg8 ^ (r & 7))) << 4);
    *(uint4*)dp = pk;
}

// ============== GEMM: h1[l][b][h] = tanh(x @ W1^T + b1), fp16 out ==============
#define ABUF_OFF 0        // 2 x 16KB
#define BBUF_OFF 32768    // 2 x 16KB
#define GEMM_SMEM 65536

extern __shared__ unsigned char gsmem[];

__global__ void __launch_bounds__(256, 2) gemm_kernel(const float* __restrict__ b1) {
    const int tid  = threadIdx.x;
    const int warp = tid >> 5;
    const int lane = tid & 31;
    const int wm   = warp & 3;      // M quarter (32 rows)
    const int wn   = warp >> 2;     // N half (64 cols)
    const int mb   = blockIdx.x & 127;
    const int nb   = blockIdx.x >> 7;
    const int nc   = (nb >> 2) + 1; // causal: # of 64-wide k-chunks needed

    const uint32_t sb = smem_u32(gsmem);

    auto pfA = [&](int kb, int buf) {
        uint32_t dst = sb + ABUF_OFF + (uint32_t)buf * 16384 + (uint32_t)tid * 64;
        const unsigned char* src = (const unsigned char*)g_xh
            + (size_t)(mb * 4 + kb) * 16384 + (size_t)tid * 64;
        #pragma unroll
        for (int i = 0; i < 4; ++i) CP_ASYNC16(dst + i * 16, src + i * 16);
    };
    auto pfB = [&](int kb, int buf) {
        uint32_t dst = sb + BBUF_OFF + (uint32_t)buf * 16384 + (uint32_t)tid * 64;
        const unsigned char* src = (const unsigned char*)g_w1t
            + (size_t)(nb * 16 + kb * 4) * 4096 + (size_t)tid * 64;
        #pragma unroll
        for (int i = 0; i < 4; ++i) CP_ASYNC16(dst + i * 16, src + i * 16);
    };

    pfA(0, 0); pfB(0, 0); CP_COMMIT();
    if (nc > 1) { pfA(1, 1); pfB(1, 1); CP_COMMIT(); }

    float acc[2][8][4];
    #pragma unroll
    for (int mt = 0; mt < 2; ++mt)
        #pragma unroll
        for (int t = 0; t < 8; ++t)
            #pragma unroll
            for (int q = 0; q < 4; ++q) acc[mt][t][q] = 0.f;

    const int arow0 = wm * 32 + (lane & 7) + ((lane >> 3) & 1) * 8;
    const int bk    = (lane & 7) + ((lane >> 3) & 1) * 8;

    for (int kb = 0; kb < nc; ++kb) {
        if (kb < nc - 1) { CP_WAIT1(); } else { CP_WAIT0(); }
        __syncthreads();
        const uint32_t aBuf = sb + ABUF_OFF + (uint32_t)(kb & 1) * 16384;
        const uint32_t bBuf = sb + BBUF_OFF + (uint32_t)(kb & 1) * 16384;
        #pragma unroll
        for (int kt = 0; kt < 4; ++kt) {
            uint32_t af[2][4], bf[4][4];
            uint32_t g = (uint32_t)(2 * kt + (lane >> 4));
            uint32_t offk = ((g ^ (uint32_t)(arow0 & 7)) << 4);
            ldsm4(af[0], aBuf + (uint32_t)arow0 * 128 + offk);
            uint32_t offk1 = ((g ^ (uint32_t)((arow0 + 16) & 7)) << 4);
            ldsm4(af[1], aBuf + (uint32_t)(arow0 + 16) * 128 + offk1);
            #pragma unroll
            for (int p = 0; p < 4; ++p) {
                uint32_t cidx = (uint32_t)(wn * 8 + 2 * p + (lane >> 4));
                ldsm4t(bf[p], bBuf + (uint32_t)kt * 4096 + (uint32_t)bk * 256
                              + ((cidx ^ (uint32_t)(lane & 7)) << 4));
            }
            #pragma unroll
            for (int mt = 0; mt < 2; ++mt)
                #pragma unroll
                for (int p = 0; p < 4; ++p) {
                    mma_f16(acc[mt][2 * p],     af[mt], &bf[p][0]);
                    mma_f16(acc[mt][2 * p + 1], af[mt], &bf[p][2]);
                }
        }
        __syncthreads();
        if (kb + 2 < nc) { pfA(kb + 2, kb & 1); pfB(kb + 2, kb & 1); CP_COMMIT(); }
    }

    // epilogue: tanh(acc + b1) -> fp16 h1, coalesced STG.32
    const int h  = (lane & 3) * 2;
    const int b0 = mb * 128 + wm * 32 + (lane >> 2);
    #pragma unroll
    for (int mt = 0; mt < 2; ++mt) {
        #pragma unroll
        for (int t = 0; t < 8; ++t) {
            int l = nb * 16 + wn * 8 + t;
            if (l < LL) {
                float2 b1v = *(const float2*)(b1 + l * 8 + h);
                int br = b0 + mt * 16;
                __half2 p01 = __floats2half2_rn(ftanha(acc[mt][t][0] + b1v.x),
                                                ftanha(acc[mt][t][1] + b1v.y));
                *(__half2*)(g_h1 + ((size_t)l * BB + br) * HH + h) = p01;
                __half2 p23 = __floats2half2_rn(ftanha(acc[mt][t][2] + b1v.x),
                                                ftanha(acc[mt][t][3] + b1v.y));
                *(__half2*)(g_h1 + ((size_t)l * BB + br + 8) * HH + h) = p23;
            }
        }
    }
}

// ============== pointwise: one CTA per layer, weights in registers ==============
__global__ void __launch_bounds__(256) zmaf2_kernel(
    const float* __restrict__ W2, const float* __restrict__ b2,
    const float* __restrict__ W3, const float* __restrict__ b3)
{
    const int l   = blockIdx.x;           // 0..254
    const int tid = threadIdx.x;

    // uniform weight loads, register-resident for the whole CTA lifetime
    unsigned long long w2u[32];           // W2[l][h][k] as f32x2 pairs
    {
        const float4* w2p = (const float4*)(W2 + l * 64);
        #pragma unroll
        for (int i = 0; i < 16; ++i) {
            float4 v = w2p[i];
            w2u[2 * i]     = pk2(v.x, v.y);
            w2u[2 * i + 1] = pk2(v.z, v.w);
        }
    }
    float4 w3r[4];
    {
        const float4* w3p = (const float4*)(W3 + l * 16);
        #pragma unroll
        for (int i = 0; i < 4; ++i) w3r[i] = w3p[i];
    }
    unsigned long long b2p[4];
    {
        float4 a = ((const float4*)(b2 + l * 8))[0];
        float4 b = ((const float4*)(b2 + l * 8))[1];
        b2p[0] = pk2(a.x, a.y); b2p[1] = pk2(a.z, a.w);
        b2p[2] = pk2(b.x, b.y); b2p[3] = pk2(b.z, b.w);
    }
    float2 b3v = *(const float2*)(b3 + l * 2);

    const __half* h1base = g_h1 + (size_t)l * BB * HH;
    float* mup = g_mu + (size_t)l * BB;
    float* alp = g_al + (size_t)l * BB;

    #pragma unroll 2
    for (int it = 0; it < 64; ++it) {
        int row = it * 256 + tid;
        uint4 q = *(const uint4*)(h1base + (size_t)row * HH);
        float2 f0 = __half22float2(*(__half2*)&q.x);
        float2 f1 = __half22float2(*(__half2*)&q.y);
        float2 f2 = __half22float2(*(__half2*)&q.z);
        float2 f3 = __half22float2(*(__half2*)&q.w);
        float h1v[8] = {f0.x, f0.y, f1.x, f1.y, f2.x, f2.y, f3.x, f3.y};

        unsigned long long a2[4] = {b2p[0], b2p[1], b2p[2], b2p[3]};
        #pragma unroll
        for (int hh = 0; hh < 8; ++hh) {
            unsigned long long hp = pk2(h1v[hh], h1v[hh]);
            fma2(a2[0], hp, w2u[hh * 4 + 0]);
            fma2(a2[1], hp, w2u[hh * 4 + 1]);
            fma2(a2[2], hp, w2u[hh * 4 + 2]);
            fma2(a2[3], hp, w2u[hh * 4 + 3]);
        }
        float mu = b3v.x, al = b3v.y;
        #pragma unroll
        for (int qq = 0; qq < 4; ++qq) {
            float2 pr = up2(a2[qq]);
            float h2a = ftanha(pr.x), h2b = ftanha(pr.y);
            mu += h2a * w3r[qq].x + h2b * w3r[qq].z;
            al += h2a * w3r[qq].y + h2b * w3r[qq].w;
        }
        mup[row] = mu;
        alp[row] = al;
    }
}

// ============== finalize: transpose + z + reversal + log_det ==============
__global__ void __launch_bounds__(256) zfin_kernel(
    const float* __restrict__ x, const float* __restrict__ ipar,
    float* __restrict__ out, int out_size)
{
    __shared__ float must[16][137];
    __shared__ float alst[16][137];

    const int tid  = threadIdx.x;
    const int row0 = blockIdx.x * 128;
    float alacc = 0.f;

    for (int lb = 0; lb < 16; ++lb) {
        __syncthreads();
        // load tile [16 l][128 rows], coalesced along rows
        #pragma unroll
        for (int i = 0; i < 8; ++i) {
            int v = tid + i * 256;
            int lc = v >> 7, r = v & 127;
            int l = lb * 16 + lc;
            float muv = 0.f, alv = 0.f;
            if (l < LL) {
                muv = g_mu[(size_t)l * BB + row0 + r];
                alv = g_al[(size_t)l * BB + row0 + r];
            }
            must[lc][r] = muv;
            alst[lc][r] = alv;
        }
        __syncthreads();
        // z compute + coalesced write: cols cb..cb+15
        const int cb = 239 - lb * 16;
        #pragma unroll
        for (int i = 0; i < 8; ++i) {
            int v = tid + i * 256;
            int r = v >> 4, cc = v & 15;
            int col = cb + cc;
            if (col >= 0) {
                int lc = 15 - cc;
                float muv = must[lc][r];
                float alv = alst[lc][r];
                // x column = l+1 = 16*lb + 16 - cc
                float xn = x[(size_t)(row0 + r) * DD + (16 * lb + 16 - cc)];
                out[(size_t)(row0 + r) * DD + col] = (xn - muv) * __expf(-alv);
            }
        }
        // alpha row-sum for this chunk (conflict-free: stride 137)
        if (tid < 128) {
            float s = 0.f;
            #pragma unroll
            for (int lc = 0; lc < 16; ++lc) s += alst[lc][tid];
            alacc += s;
        }
    }

    if (tid < 128) {
        int rg = row0 + tid;
        float ip0 = ipar[0], ip1 = ipar[1];
        out[(size_t)rg * DD + 255] = (x[(size_t)rg * DD] - ip0) * __expf(-ip1);
        if (out_size > BB * DD)
            out[(size_t)BB * DD + rg] = -(ip1 + alacc);
    }
}

extern "C" void kernel_launch(void* const* d_in, const int* in_sizes, int n_in,
                              void* d_out, int out_size)
{
    const float* x    = (const float*)d_in[0];
    const float* ipar = (const float*)d_in[1];
    const float* W1   = (const float*)d_in[2];
    const float* b1   = (const float*)d_in[3];
    const float* W2   = (const float*)d_in[4];
    const float* b2   = (const float*)d_in[5];
    const float* W3   = (const float*)d_in[6];
    const float* b3   = (const float*)d_in[7];
    float* out = (float*)d_out;

    prep_w1<<<dim3(16, 16), 256>>>(W1);
    prep_x<<<2048, 256>>>(x);
    cudaFuncSetAttribute(gemm_kernel, cudaFuncAttributeMaxDynamicSharedMemorySize, GEMM_SMEM);
    gemm_kernel<<<2048, 256, GEMM_SMEM>>>(b1);
    zmaf2_kernel<<<LL, 256>>>(W2, b2, W3, b3);
    zfin_kernel<<<BB / 128, 256>>>(x, ipar, out, out_size);
}

// round 13
// speedup vs baseline: 2.0496x; 2.0496x over previous
#include <cuda_runtime.h>
#include <cuda_fp16.h>
#include <cstdint>
#include <cstddef>

// Problem constants
#define BB 16384
#define DD 256
#define LL 255
#define HH 8

// ---- device scratch ----
__device__ __align__(16) __half g_w1t[16 * 16 * 2048];
__device__ __align__(16) __half g_xh[128 * 4 * 8192];
__device__ __align__(16) __half g_h1[(size_t)LL * BB * HH];

// ============================ helpers ============================
__device__ __forceinline__ uint32_t smem_u32(const void* p) {
    uint32_t a;
    asm("{ .reg .u64 t; cvta.to.shared.u64 t, %1; cvt.u32.u64 %0, t; }" : "=r"(a) : "l"(p));
    return a;
}
__device__ __forceinline__ unsigned long long pk2(float a, float b) {
    unsigned long long r;
    asm("mov.b64 %0, {%1, %2};" : "=l"(r) : "f"(a), "f"(b));
    return r;
}
__device__ __forceinline__ void fma2(unsigned long long& d, unsigned long long a, unsigned long long b) {
    asm("fma.rn.f32x2 %0, %1, %2, %0;" : "+l"(d) : "l"(a), "l"(b));
}
__device__ __forceinline__ float2 up2(unsigned long long v) {
    float2 r;
    asm("mov.b64 {%0, %1}, %2;" : "=f"(r.x), "=f"(r.y) : "l"(v));
    return r;
}
__device__ __forceinline__ float ftanha(float v) {
    float r;
    asm("tanh.approx.f32 %0, %1;" : "=f"(r) : "f"(v));
    return r;
}
__device__ __forceinline__ void ldsm4(uint32_t* r, uint32_t a) {
    asm volatile("ldmatrix.sync.aligned.m8n8.x4.shared.b16 {%0,%1,%2,%3}, [%4];"
                 : "=r"(r[0]), "=r"(r[1]), "=r"(r[2]), "=r"(r[3]) : "r"(a));
}
__device__ __forceinline__ void ldsm4t(uint32_t* r, uint32_t a) {
    asm volatile("ldmatrix.sync.aligned.m8n8.x4.trans.shared.b16 {%0,%1,%2,%3}, [%4];"
                 : "=r"(r[0]), "=r"(r[1]), "=r"(r[2]), "=r"(r[3]) : "r"(a));
}
__device__ __forceinline__ void mma_f16(float* d, const uint32_t* a, const uint32_t* b) {
    asm volatile("mma.sync.aligned.m16n8k16.row.col.f32.f16.f16.f32 "
                 "{%0,%1,%2,%3}, {%4,%5,%6,%7}, {%8,%9}, {%0,%1,%2,%3};"
                 : "+f"(d[0]), "+f"(d[1]), "+f"(d[2]), "+f"(d[3])
                 : "r"(a[0]), "r"(a[1]), "r"(a[2]), "r"(a[3]), "r"(b[0]), "r"(b[1]));
}
#define CP_ASYNC16(dst, src) \
    asm volatile("cp.async.cg.shared.global [%0], [%1], 16;" :: "r"(dst), "l"(src))
#define CP_COMMIT() asm volatile("cp.async.commit_group;" ::: "memory")
#define CP_WAIT1()  asm volatile("cp.async.wait_group 1;" ::: "memory")
#define CP_WAIT0()  asm volatile("cp.async.wait_group 0;" ::: "memory")

// ============== prep 1: W1 -> fp16 causal-masked swizzled tiles ==============
__global__ void __launch_bounds__(256) prep_w1(const float* __restrict__ W1) {
    const int nb = blockIdx.x, ks = blockIdx.y;
    __half* dst = g_w1t + (nb * 16 + ks) * 2048;
    #pragma unroll
    for (int i = 0; i < 8; ++i) {
        int e = threadIdx.x + i * 256;        // 0..2047 = 16k x 128n
        int k = e >> 7, nl = e & 127;
        int l = nb * 16 + (nl >> 3), h = nl & 7;
        int kg = ks * 16 + k;
        float v = (l < LL && kg <= l) ? W1[((size_t)l * DD + kg) * HH + h] : 0.f;
        uint32_t off = (uint32_t)k * 128 + ((((nl >> 3) ^ (k & 7))) << 3) + (nl & 7);
        dst[off] = __float2half(v);
    }
}

// ============== prep 2: x -> fp16 swizzled k-chunk tiles ==============
__global__ void __launch_bounds__(256) prep_x(const float* __restrict__ x) {
    int t = blockIdx.x * 256 + threadIdx.x;   // 524288 store-units of 16B
    int kg8 = t & 7;
    int r   = (t >> 3) & 127;
    int kbmb = t >> 10;
    int kb = kbmb & 3, mb = kbmb >> 2;
    const float* src = x + ((size_t)(mb * 128 + r) * DD + kb * 64 + kg8 * 8);
    float4 v0 = *(const float4*)src;
    float4 v1 = *(const float4*)(src + 4);
    __half2 h0 = __floats2half2_rn(v0.x, v0.y);
    __half2 h1 = __floats2half2_rn(v0.z, v0.w);
    __half2 h2 = __floats2half2_rn(v1.x, v1.y);
    __half2 h3 = __floats2half2_rn(v1.z, v1.w);
    uint4 pk = make_uint4(*(uint32_t*)&h0, *(uint32_t*)&h1, *(uint32_t*)&h2, *(uint32_t*)&h3);
    unsigned char* dp = (unsigned char*)g_xh + (size_t)(mb * 4 + kb) * 16384
                      + (uint32_t)r * 128 + (((uint32_t)(kg8 ^ (r & 7))) << 4);
    *(uint4*)dp = pk;
}

// ============== GEMM: h1[l][b][h] = tanh(x @ W1^T + b1), fp16 out ==============
#define ABUF_OFF 0        // 2 x 16KB
#define BBUF_OFF 32768    // 2 x 16KB
#define GEMM_SMEM 65536

extern __shared__ unsigned char gsmem[];

__global__ void __launch_bounds__(256, 2) gemm_kernel(const float* __restrict__ b1) {
    const int tid  = threadIdx.x;
    const int warp = tid >> 5;
    const int lane = tid & 31;
    const int wm   = warp & 3;      // M quarter (32 rows)
    const int wn   = warp >> 2;     // N half (64 cols)
    const int mb   = blockIdx.x & 127;
    const int nb   = blockIdx.x >> 7;
    const int nc   = (nb >> 2) + 1; // causal: # of 64-wide k-chunks needed

    const uint32_t sb = smem_u32(gsmem);

    auto pfA = [&](int kb, int buf) {
        uint32_t dst = sb + ABUF_OFF + (uint32_t)buf * 16384 + (uint32_t)tid * 64;
        const unsigned char* src = (const unsigned char*)g_xh
            + (size_t)(mb * 4 + kb) * 16384 + (size_t)tid * 64;
        #pragma unroll
        for (int i = 0; i < 4; ++i) CP_ASYNC16(dst + i * 16, src + i * 16);
    };
    auto pfB = [&](int kb, int buf) {
        uint32_t dst = sb + BBUF_OFF + (uint32_t)buf * 16384 + (uint32_t)tid * 64;
        const unsigned char* src = (const unsigned char*)g_w1t
            + (size_t)(nb * 16 + kb * 4) * 4096 + (size_t)tid * 64;
        #pragma unroll
        for (int i = 0; i < 4; ++i) CP_ASYNC16(dst + i * 16, src + i * 16);
    };

    pfA(0, 0); pfB(0, 0); CP_COMMIT();
    if (nc > 1) { pfA(1, 1); pfB(1, 1); CP_COMMIT(); }

    float acc[2][8][4];
    #pragma unroll
    for (int mt = 0; mt < 2; ++mt)
        #pragma unroll
        for (int t = 0; t < 8; ++t)
            #pragma unroll
            for (int q = 0; q < 4; ++q) acc[mt][t][q] = 0.f;

    const int arow0 = wm * 32 + (lane & 7) + ((lane >> 3) & 1) * 8;
    const int bk    = (lane & 7) + ((lane >> 3) & 1) * 8;

    for (int kb = 0; kb < nc; ++kb) {
        if (kb < nc - 1) { CP_WAIT1(); } else { CP_WAIT0(); }
        __syncthreads();
        const uint32_t aBuf = sb + ABUF_OFF + (uint32_t)(kb & 1) * 16384;
        const uint32_t bBuf = sb + BBUF_OFF + (uint32_t)(kb & 1) * 16384;
        #pragma unroll
        for (int kt = 0; kt < 4; ++kt) {
            uint32_t af[2][4], bf[4][4];
            uint32_t g = (uint32_t)(2 * kt + (lane >> 4));
            uint32_t offk = ((g ^ (uint32_t)(arow0 & 7)) << 4);
            ldsm4(af[0], aBuf + (uint32_t)arow0 * 128 + offk);
            uint32_t offk1 = ((g ^ (uint32_t)((arow0 + 16) & 7)) << 4);
            ldsm4(af[1], aBuf + (uint32_t)(arow0 + 16) * 128 + offk1);
            #pragma unroll
            for (int p = 0; p < 4; ++p) {
                uint32_t cidx = (uint32_t)(wn * 8 + 2 * p + (lane >> 4));
                ldsm4t(bf[p], bBuf + (uint32_t)kt * 4096 + (uint32_t)bk * 256
                              + ((cidx ^ (uint32_t)(lane & 7)) << 4));
            }
            #pragma unroll
            for (int mt = 0; mt < 2; ++mt)
                #pragma unroll
                for (int p = 0; p < 4; ++p) {
                    mma_f16(acc[mt][2 * p],     af[mt], &bf[p][0]);
                    mma_f16(acc[mt][2 * p + 1], af[mt], &bf[p][2]);
                }
        }
        __syncthreads();
        if (kb + 2 < nc) { pfA(kb + 2, kb & 1); pfB(kb + 2, kb & 1); CP_COMMIT(); }
    }

    // epilogue: tanh(acc + b1) -> fp16 h1, coalesced STG.32
    const int h  = (lane & 3) * 2;
    const int b0 = mb * 128 + wm * 32 + (lane >> 2);
    #pragma unroll
    for (int mt = 0; mt < 2; ++mt) {
        #pragma unroll
        for (int t = 0; t < 8; ++t) {
            int l = nb * 16 + wn * 8 + t;
            if (l < LL) {
                float2 b1v = *(const float2*)(b1 + l * 8 + h);
                int br = b0 + mt * 16;
                __half2 p01 = __floats2half2_rn(ftanha(acc[mt][t][0] + b1v.x),
                                                ftanha(acc[mt][t][1] + b1v.y));
                *(__half2*)(g_h1 + ((size_t)l * BB + br) * HH + h) = p01;
                __half2 p23 = __floats2half2_rn(ftanha(acc[mt][t][2] + b1v.x),
                                                ftanha(acc[mt][t][3] + b1v.y));
                *(__half2*)(g_h1 + ((size_t)l * BB + br + 8) * HH + h) = p23;
            }
        }
    }
}

// ============== pointwise: 64 rows/CTA, weights register-amortized over 8 rows ==============
#define ZS 35   // smem stride

__global__ void __launch_bounds__(256, 2) zmaf4_kernel(
    const float* __restrict__ x,  const float* __restrict__ ipar,
    const float* __restrict__ W2, const float* __restrict__ b2,
    const float* __restrict__ W3, const float* __restrict__ b3,
    float* __restrict__ out, int out_size)
{
    __shared__ float zst[64 * ZS];
    __shared__ float xs[64 * ZS];
    __shared__ float as_[64 * ZS];

    const int tid  = threadIdx.x;
    const int lane = tid & 31;
    const int warp = tid >> 5;
    const int j32  = warp * 4 + (lane >> 3);   // 0..31 layer lane
    const int slot = lane & 7;                 // row slot
    const int row0 = blockIdx.x * 64;

    float alacc[8];
    #pragma unroll
    for (int i = 0; i < 8; ++i) alacc[i] = 0.f;

    for (int s = 0; s < 8; ++s) {
        const int l   = s * 32 + j32;
        const bool act = (l < LL);
        const int lw  = act ? l : 0;

        __syncthreads();   // previous flush done before zst/xs rewrite
        // stage x columns s*32+1 .. s*32+32 (coalesced)
        #pragma unroll
        for (int it = 0; it < 8; ++it) {
            int v = tid + it * 256;
            int r = v >> 5, cc = v & 31;
            int col = s * 32 + 1 + cc;
            xs[r * ZS + cc] = (col < DD) ? x[(size_t)(row0 + r) * DD + col] : 0.f;
        }

        // weights for layer l -> registers (amortized over 8 rows)
        unsigned long long w2u[32];
        {
            const float4* w2p = (const float4*)(W2 + lw * 64);
            #pragma unroll
            for (int i = 0; i < 16; ++i) {
                float4 v = w2p[i];
                w2u[2 * i]     = pk2(v.x, v.y);
                w2u[2 * i + 1] = pk2(v.z, v.w);
            }
        }
        float4 w3r[4];
        {
            const float4* w3p = (const float4*)(W3 + lw * 16);
            #pragma unroll
            for (int i = 0; i < 4; ++i) w3r[i] = w3p[i];
        }
        unsigned long long b2p[4];
        {
            float4 a = ((const float4*)(b2 + lw * 8))[0];
            float4 b = ((const float4*)(b2 + lw * 8))[1];
            b2p[0] = pk2(a.x, a.y); b2p[1] = pk2(a.z, a.w);
            b2p[2] = pk2(b.x, b.y); b2p[3] = pk2(b.z, b.w);
        }
        float2 b3v = *(const float2*)(b3 + lw * 2);

        __syncthreads();   // xs visible

        if (act) {
            const __half* h1base = g_h1 + (size_t)l * BB * HH + (size_t)row0 * HH;
            #pragma unroll
            for (int i = 0; i < 8; ++i) {
                int row = slot + 8 * i;
                uint4 q = *(const uint4*)(h1base + (size_t)row * HH);
                float2 f0 = __half22float2(*(__half2*)&q.x);
                float2 f1 = __half22float2(*(__half2*)&q.y);
                float2 f2 = __half22float2(*(__half2*)&q.z);
                float2 f3 = __half22float2(*(__half2*)&q.w);
                float h1v[8] = {f0.x, f0.y, f1.x, f1.y, f2.x, f2.y, f3.x, f3.y};

                unsigned long long a2[4] = {b2p[0], b2p[1], b2p[2], b2p[3]};
                #pragma unroll
                for (int hh = 0; hh < 8; ++hh) {
                    unsigned long long hp = pk2(h1v[hh], h1v[hh]);
                    fma2(a2[0], hp, w2u[hh * 4 + 0]);
                    fma2(a2[1], hp, w2u[hh * 4 + 1]);
                    fma2(a2[2], hp, w2u[hh * 4 + 2]);
                    fma2(a2[3], hp, w2u[hh * 4 + 3]);
                }
                float mu = b3v.x, al = b3v.y;
                #pragma unroll
                for (int qq = 0; qq < 4; ++qq) {
                    float2 pr = up2(a2[qq]);
                    float h2a = ftanha(pr.x), h2b = ftanha(pr.y);
                    mu += h2a * w3r[qq].x + h2b * w3r[qq].z;
                    al += h2a * w3r[qq].y + h2b * w3r[qq].w;
                }
                float xn = xs[row * ZS + j32];
                zst[row * ZS + j32] = (xn - mu) * __expf(-al);
                alacc[i] += al;
            }
        }

        __syncthreads();   // zst complete
        // flush: out cols 223-32s .. 254-32s (coalesced, reversed layers)
        #pragma unroll
        for (int it = 0; it < 8; ++it) {
            int v = tid + it * 256;
            int r = v >> 5, cc = v & 31;
            int col = 223 - 32 * s + cc;
            if (col >= 0)
                out[(size_t)(row0 + r) * DD + col] = zst[r * ZS + (31 - cc)];
        }
    }

    // alpha reduce + finals
    __syncthreads();
    #pragma unroll
    for (int i = 0; i < 8; ++i)
        as_[(slot + 8 * i) * ZS + j32] = alacc[i];
    __syncthreads();
    if (tid < 64) {
        float ssum = 0.f;
        #pragma unroll
        for (int qq = 0; qq < 32; ++qq) ssum += as_[tid * ZS + qq];
        int rg = row0 + tid;
        float ip0 = ipar[0], ip1 = ipar[1];
        out[(size_t)rg * DD + 255] = (x[(size_t)rg * DD] - ip0) * __expf(-ip1);
        if (out_size > BB * DD)
            out[(size_t)BB * DD + rg] = -(ip1 + ssum);
    }
}

extern "C" void kernel_launch(void* const* d_in, const int* in_sizes, int n_in,
                              void* d_out, int out_size)
{
    const float* x    = (const float*)d_in[0];
    const float* ipar = (const float*)d_in[1];
    const float* W1   = (const float*)d_in[2];
    const float* b1   = (const float*)d_in[3];
    const float* W2   = (const float*)d_in[4];
    const float* b2   = (const float*)d_in[5];
    const float* W3   = (const float*)d_in[6];
    const float* b3   = (const float*)d_in[7];
    float* out = (float*)d_out;

    prep_w1<<<dim3(16, 16), 256>>>(W1);
    prep_x<<<2048, 256>>>(x);
    cudaFuncSetAttribute(gemm_kernel, cudaFuncAttributeMaxDynamicSharedMemorySize, GEMM_SMEM);
    gemm_kernel<<<2048, 256, GEMM_SMEM>>>(b1);
    zmaf4_kernel<<<BB / 64, 256>>>(x, ipar, W2, b2, W3, b3, out, out_size);
}

// round 14
// speedup vs baseline: 2.6641x; 1.2998x over previous
#include <cuda_runtime.h>
#include <cuda_fp16.h>
#include <cstdint>
#include <cstddef>

// Problem constants
#define BB 16384
#define DD 256
#define LL 255
#define HH 8

// ---- device scratch ----
__device__ __align__(16) __half g_w1t[16 * 16 * 2048];
__device__ __align__(16) __half g_xh[128 * 4 * 8192];
__device__ __align__(16) float  g_apart[16 * BB];   // per-nb alpha partials

// ============================ helpers ============================
__device__ __forceinline__ uint32_t smem_u32(const void* p) {
    uint32_t a;
    asm("{ .reg .u64 t; cvta.to.shared.u64 t, %1; cvt.u32.u64 %0, t; }" : "=r"(a) : "l"(p));
    return a;
}
__device__ __forceinline__ unsigned long long pk2(float a, float b) {
    unsigned long long r;
    asm("mov.b64 %0, {%1, %2};" : "=l"(r) : "f"(a), "f"(b));
    return r;
}
__device__ __forceinline__ void fma2(unsigned long long& d, unsigned long long a, unsigned long long b) {
    asm("fma.rn.f32x2 %0, %1, %2, %0;" : "+l"(d) : "l"(a), "l"(b));
}
__device__ __forceinline__ float2 up2(unsigned long long v) {
    float2 r;
    asm("mov.b64 {%0, %1}, %2;" : "=f"(r.x), "=f"(r.y) : "l"(v));
    return r;
}
__device__ __forceinline__ float ftanha(float v) {
    float r;
    asm("tanh.approx.f32 %0, %1;" : "=f"(r) : "f"(v));
    return r;
}
__device__ __forceinline__ void ldsm4(uint32_t* r, uint32_t a) {
    asm volatile("ldmatrix.sync.aligned.m8n8.x4.shared.b16 {%0,%1,%2,%3}, [%4];"
                 : "=r"(r[0]), "=r"(r[1]), "=r"(r[2]), "=r"(r[3]) : "r"(a));
}
__device__ __forceinline__ void ldsm4t(uint32_t* r, uint32_t a) {
    asm volatile("ldmatrix.sync.aligned.m8n8.x4.trans.shared.b16 {%0,%1,%2,%3}, [%4];"
                 : "=r"(r[0]), "=r"(r[1]), "=r"(r[2]), "=r"(r[3]) : "r"(a));
}
__device__ __forceinline__ void mma_f16(float* d, const uint32_t* a, const uint32_t* b) {
    asm volatile("mma.sync.aligned.m16n8k16.row.col.f32.f16.f16.f32 "
                 "{%0,%1,%2,%3}, {%4,%5,%6,%7}, {%8,%9}, {%0,%1,%2,%3};"
                 : "+f"(d[0]), "+f"(d[1]), "+f"(d[2]), "+f"(d[3])
                 : "r"(a[0]), "r"(a[1]), "r"(a[2]), "r"(a[3]), "r"(b[0]), "r"(b[1]));
}
#define CP_ASYNC16(dst, src) \
    asm volatile("cp.async.cg.shared.global [%0], [%1], 16;" :: "r"(dst), "l"(src))
#define CP_COMMIT() asm volatile("cp.async.commit_group;" ::: "memory")
#define CP_WAIT1()  asm volatile("cp.async.wait_group 1;" ::: "memory")
#define CP_WAIT0()  asm volatile("cp.async.wait_group 0;" ::: "memory")

// ============== prep 1: W1 -> fp16 causal-masked swizzled tiles ==============
__global__ void __launch_bounds__(256) prep_w1(const float* __restrict__ W1) {
    const int nb = blockIdx.x, ks = blockIdx.y;
    __half* dst = g_w1t + (nb * 16 + ks) * 2048;
    #pragma unroll
    for (int i = 0; i < 8; ++i) {
        int e = threadIdx.x + i * 256;        // 0..2047 = 16k x 128n
        int k = e >> 7, nl = e & 127;
        int l = nb * 16 + (nl >> 3), h = nl & 7;
        int kg = ks * 16 + k;
        float v = (l < LL && kg <= l) ? W1[((size_t)l * DD + kg) * HH + h] : 0.f;
        uint32_t off = (uint32_t)k * 128 + ((((nl >> 3) ^ (k & 7))) << 3) + (nl & 7);
        dst[off] = __float2half(v);
    }
}

// ============== prep 2: x -> fp16 swizzled k-chunk tiles ==============
__global__ void __launch_bounds__(256) prep_x(const float* __restrict__ x) {
    int t = blockIdx.x * 256 + threadIdx.x;   // 524288 store-units of 16B
    int kg8 = t & 7;
    int r   = (t >> 3) & 127;
    int kbmb = t >> 10;
    int kb = kbmb & 3, mb = kbmb >> 2;
    const float* src = x + ((size_t)(mb * 128 + r) * DD + kb * 64 + kg8 * 8);
    float4 v0 = *(const float4*)src;
    float4 v1 = *(const float4*)(src + 4);
    __half2 h0 = __floats2half2_rn(v0.x, v0.y);
    __half2 h1 = __floats2half2_rn(v0.z, v0.w);
    __half2 h2 = __floats2half2_rn(v1.x, v1.y);
    __half2 h3 = __floats2half2_rn(v1.z, v1.w);
    uint4 pk = make_uint4(*(uint32_t*)&h0, *(uint32_t*)&h1, *(uint32_t*)&h2, *(uint32_t*)&h3);
    unsigned char* dp = (unsigned char*)g_xh + (size_t)(mb * 4 + kb) * 16384
                      + (uint32_t)r * 128 + (((uint32_t)(kg8 ^ (r & 7))) << 4);
    *(uint4*)dp = pk;
}

// ============== fused GEMM + MLP + z ==============
#define ABUF_OFF 0        // 2 x 16KB
#define BBUF_OFF 32768    // 2 x 16KB
// epilogue layout (overlaps the dead A/B buffers)
#define STG2_OFF 0        // 128 x 132 fp32 h1  (67584B)
#define XS2_OFF  67584    // 128 x 17 fp32      (8704B)
#define ZST_OFF  76288    // 128 x 17 fp32
#define AS2_OFF  84992    // 128 x 17 fp32
#define GEMM_SMEM 93696

extern __shared__ unsigned char gsmem[];

__global__ void __launch_bounds__(256, 2) gemm_kernel(
    const float* __restrict__ x,  const float* __restrict__ b1,
    const float* __restrict__ W2, const float* __restrict__ b2,
    const float* __restrict__ W3, const float* __restrict__ b3,
    float* __restrict__ out)
{
    const int tid  = threadIdx.x;
    const int warp = tid >> 5;
    const int lane = tid & 31;
    const int wm   = warp & 3;      // M quarter (32 rows)
    const int wn   = warp >> 2;     // N half (64 cols)
    const int mb   = blockIdx.x & 127;
    const int nb   = blockIdx.x >> 7;
    const int nc   = (nb >> 2) + 1; // causal: # of 64-wide k-chunks needed

    const uint32_t sb = smem_u32(gsmem);

    auto pfA = [&](int kb, int buf) {
        uint32_t dst = sb + ABUF_OFF + (uint32_t)buf * 16384 + (uint32_t)tid * 64;
        const unsigned char* src = (const unsigned char*)g_xh
            + (size_t)(mb * 4 + kb) * 16384 + (size_t)tid * 64;
        #pragma unroll
        for (int i = 0; i < 4; ++i) CP_ASYNC16(dst + i * 16, src + i * 16);
    };
    auto pfB = [&](int kb, int buf) {
        uint32_t dst = sb + BBUF_OFF + (uint32_t)buf * 16384 + (uint32_t)tid * 64;
        const unsigned char* src = (const unsigned char*)g_w1t
            + (size_t)(nb * 16 + kb * 4) * 4096 + (size_t)tid * 64;
        #pragma unroll
        for (int i = 0; i < 4; ++i) CP_ASYNC16(dst + i * 16, src + i * 16);
    };

    pfA(0, 0); pfB(0, 0); CP_COMMIT();
    if (nc > 1) { pfA(1, 1); pfB(1, 1); CP_COMMIT(); }

    float acc[2][8][4];
    #pragma unroll
    for (int mt = 0; mt < 2; ++mt)
        #pragma unroll
        for (int t = 0; t < 8; ++t)
            #pragma unroll
            for (int q = 0; q < 4; ++q) acc[mt][t][q] = 0.f;

    const int arow0 = wm * 32 + (lane & 7) + ((lane >> 3) & 1) * 8;
    const int bk    = (lane & 7) + ((lane >> 3) & 1) * 8;

    for (int kb = 0; kb < nc; ++kb) {
        if (kb < nc - 1) { CP_WAIT1(); } else { CP_WAIT0(); }
        __syncthreads();
        const uint32_t aBuf = sb + ABUF_OFF + (uint32_t)(kb & 1) * 16384;
        const uint32_t bBuf = sb + BBUF_OFF + (uint32_t)(kb & 1) * 16384;
        #pragma unroll
        for (int kt = 0; kt < 4; ++kt) {
            uint32_t af[2][4], bf[4][4];
            uint32_t g = (uint32_t)(2 * kt + (lane >> 4));
            uint32_t offk = ((g ^ (uint32_t)(arow0 & 7)) << 4);
            ldsm4(af[0], aBuf + (uint32_t)arow0 * 128 + offk);
            uint32_t offk1 = ((g ^ (uint32_t)((arow0 + 16) & 7)) << 4);
            ldsm4(af[1], aBuf + (uint32_t)(arow0 + 16) * 128 + offk1);
            #pragma unroll
            for (int p = 0; p < 4; ++p) {
                uint32_t cidx = (uint32_t)(wn * 8 + 2 * p + (lane >> 4));
                ldsm4t(bf[p], bBuf + (uint32_t)kt * 4096 + (uint32_t)bk * 256
                              + ((cidx ^ (uint32_t)(lane & 7)) << 4));
            }
            #pragma unroll
            for (int mt = 0; mt < 2; ++mt)
                #pragma unroll
                for (int p = 0; p < 4; ++p) {
                    mma_f16(acc[mt][2 * p],     af[mt], &bf[p][0]);
                    mma_f16(acc[mt][2 * p + 1], af[mt], &bf[p][2]);
                }
        }
        __syncthreads();
        if (kb + 2 < nc) { pfA(kb + 2, kb & 1); pfB(kb + 2, kb & 1); CP_COMMIT(); }
    }
    // after the loop's trailing __syncthreads, A/B buffers are dead -> reuse as stg

    float* stg = (float*)(gsmem + STG2_OFF);   // [128][132] fp32 h1
    float* xs  = (float*)(gsmem + XS2_OFF);    // [128][17]
    float* zst = (float*)(gsmem + ZST_OFF);    // [128][17]
    float* as2 = (float*)(gsmem + AS2_OFF);    // [128][17]

    // ---- stage h1 = tanh(acc + b1) (fragment -> smem, R11-verified mapping) ----
    {
        const int h  = (lane & 3) * 2;
        const int r0 = wm * 32 + (lane >> 2);
        #pragma unroll
        for (int t = 0; t < 8; ++t) {
            int l = nb * 16 + wn * 8 + t;
            float2 b1v = make_float2(0.f, 0.f);
            if (l < LL) b1v = *(const float2*)(b1 + l * 8 + h);
            int ln = (wn * 8 + t) * 8 + h;
            #pragma unroll
            for (int mt = 0; mt < 2; ++mt) {
                *(float2*)(stg + (r0 + mt * 16) * 132 + ln) =
                    make_float2(ftanha(acc[mt][t][0] + b1v.x),
                                ftanha(acc[mt][t][1] + b1v.y));
                *(float2*)(stg + (r0 + mt * 16 + 8) * 132 + ln) =
                    make_float2(ftanha(acc[mt][t][2] + b1v.x),
                                ftanha(acc[mt][t][3] + b1v.y));
            }
        }
    }
    // ---- stage x columns nb*16+1 .. nb*16+16 ----
    #pragma unroll
    for (int i = 0; i < 8; ++i) {
        int v = tid + i * 256;
        int r = v >> 4, cc = v & 15;
        int col = nb * 16 + 1 + cc;
        xs[r * 17 + cc] = (col < DD) ? x[(size_t)(mb * 128 + r) * DD + col] : 0.f;
    }
    __syncthreads();

    // ---- MLP jobs: thread = (layer-lane jl, slot), 8 rows each ----
    {
        const int jl   = tid >> 4;          // 0..15
        const int slot = tid & 15;
        const int l    = nb * 16 + jl;
        const bool act = (l < LL);
        const int lw   = act ? l : 0;

        unsigned long long w2u[32];
        {
            const float4* w2p = (const float4*)(W2 + lw * 64);
            #pragma unroll
            for (int i = 0; i < 16; ++i) {
                float4 v = w2p[i];
                w2u[2 * i]     = pk2(v.x, v.y);
                w2u[2 * i + 1] = pk2(v.z, v.w);
            }
        }
        float4 w3r[4];
        {
            const float4* w3p = (const float4*)(W3 + lw * 16);
            #pragma unroll
            for (int i = 0; i < 4; ++i) w3r[i] = w3p[i];
        }
        unsigned long long b2p[4];
        {
            float4 a = ((const float4*)(b2 + lw * 8))[0];
            float4 b = ((const float4*)(b2 + lw * 8))[1];
            b2p[0] = pk2(a.x, a.y); b2p[1] = pk2(a.z, a.w);
            b2p[2] = pk2(b.x, b.y); b2p[3] = pk2(b.z, b.w);
        }
        float2 b3v = *(const float2*)(b3 + lw * 2);

        #pragma unroll
        for (int i = 0; i < 8; ++i) {
            int row = slot + 16 * i;
            if (act) {
                float4 q0 = *(const float4*)(stg + row * 132 + jl * 8);
                float4 q1 = *(const float4*)(stg + row * 132 + jl * 8 + 4);
                float h1v[8] = {q0.x, q0.y, q0.z, q0.w, q1.x, q1.y, q1.z, q1.w};

                unsigned long long a2[4] = {b2p[0], b2p[1], b2p[2], b2p[3]};
                #pragma unroll
                for (int hh = 0; hh < 8; ++hh) {
                    unsigned long long hp = pk2(h1v[hh], h1v[hh]);
                    fma2(a2[0], hp, w2u[hh * 4 + 0]);
                    fma2(a2[1], hp, w2u[hh * 4 + 1]);
                    fma2(a2[2], hp, w2u[hh * 4 + 2]);
                    fma2(a2[3], hp, w2u[hh * 4 + 3]);
                }
                float mu = b3v.x, al = b3v.y;
                #pragma unroll
                for (int qq = 0; qq < 4; ++qq) {
                    float2 pr = up2(a2[qq]);
                    float h2a = ftanha(pr.x), h2b = ftanha(pr.y);
                    mu += h2a * w3r[qq].x + h2b * w3r[qq].z;
                    al += h2a * w3r[qq].y + h2b * w3r[qq].w;
                }
                float xn = xs[row * 17 + jl];
                zst[row * 17 + jl] = (xn - mu) * __expf(-al);
                as2[row * 17 + jl] = al;
            } else {
                as2[row * 17 + jl] = 0.f;
            }
        }
    }
    __syncthreads();

    // ---- flush z (coalesced, reversed) + alpha partial ----
    #pragma unroll
    for (int it = 0; it < 8; ++it) {
        int v = tid + it * 256;
        int r = v >> 4, cc = v & 15;
        int col = 239 - nb * 16 + cc;
        if (col >= 0)
            out[(size_t)(mb * 128 + r) * DD + col] = zst[r * 17 + (15 - cc)];
    }
    if (tid < 128) {
        float s = 0.f;
        #pragma unroll
        for (int jl = 0; jl < 16; ++jl) s += as2[tid * 17 + jl];
        g_apart[nb * BB + mb * 128 + tid] = s;
    }
}

// ============== final: col 255 + log_det (deterministic 16-way sum) ==============
__global__ void __launch_bounds__(512) zfinal_kernel(
    const float* __restrict__ x, const float* __restrict__ ipar,
    float* __restrict__ out, int out_size)
{
    int r = blockIdx.x * 512 + threadIdx.x;
    float s = 0.f;
    #pragma unroll
    for (int nb = 0; nb < 16; ++nb) s += g_apart[nb * BB + r];
    float ip0 = ipar[0], ip1 = ipar[1];
    out[(size_t)r * DD + 255] = (x[(size_t)r * DD] - ip0) * __expf(-ip1);
    if (out_size > BB * DD)
        out[(size_t)BB * DD + r] = -(ip1 + s);
}

extern "C" void kernel_launch(void* const* d_in, const int* in_sizes, int n_in,
                              void* d_out, int out_size)
{
    const float* x    = (const float*)d_in[0];
    const float* ipar = (const float*)d_in[1];
    const float* W1   = (const float*)d_in[2];
    const float* b1   = (const float*)d_in[3];
    const float* W2   = (const float*)d_in[4];
    const float* b2   = (const float*)d_in[5];
    const float* W3   = (const float*)d_in[6];
    const float* b3   = (const float*)d_in[7];
    float* out = (float*)d_out;

    prep_w1<<<dim3(16, 16), 256>>>(W1);
    prep_x<<<2048, 256>>>(x);
    cudaFuncSetAttribute(gemm_kernel, cudaFuncAttributeMaxDynamicSharedMemorySize, GEMM_SMEM);
    gemm_kernel<<<2048, 256, GEMM_SMEM>>>(x, b1, W2, b2, W3, b3, out);
    zfinal_kernel<<<BB / 512, 512>>>(x, ipar, out, out_size);
}

// round 15
// speedup vs baseline: 2.7009x; 1.0138x over previous
#include <cuda_runtime.h>
#include <cuda_fp16.h>
#include <cstdint>
#include <cstddef>

// Problem constants
#define BB 16384
#define DD 256
#define LL 255
#define HH 8

// ---- device scratch ----
__device__ __align__(16) __half g_w1t[16 * 16 * 2048];
__device__ __align__(16) __half g_xh[128 * 4 * 8192];
__device__ __align__(16) float  g_apart[16 * BB];   // per-nb alpha partials

// ============================ helpers ============================
__device__ __forceinline__ uint32_t smem_u32(const void* p) {
    uint32_t a;
    asm("{ .reg .u64 t; cvta.to.shared.u64 t, %1; cvt.u32.u64 %0, t; }" : "=r"(a) : "l"(p));
    return a;
}
__device__ __forceinline__ unsigned long long pk2(float a, float b) {
    unsigned long long r;
    asm("mov.b64 %0, {%1, %2};" : "=l"(r) : "f"(a), "f"(b));
    return r;
}
__device__ __forceinline__ void fma2(unsigned long long& d, unsigned long long a, unsigned long long b) {
    asm("fma.rn.f32x2 %0, %1, %2, %0;" : "+l"(d) : "l"(a), "l"(b));
}
__device__ __forceinline__ float2 up2(unsigned long long v) {
    float2 r;
    asm("mov.b64 {%0, %1}, %2;" : "=f"(r.x), "=f"(r.y) : "l"(v));
    return r;
}
__device__ __forceinline__ float ftanha(float v) {
    float r;
    asm("tanh.approx.f32 %0, %1;" : "=f"(r) : "f"(v));
    return r;
}
__device__ __forceinline__ void ldsm4(uint32_t* r, uint32_t a) {
    asm volatile("ldmatrix.sync.aligned.m8n8.x4.shared.b16 {%0,%1,%2,%3}, [%4];"
                 : "=r"(r[0]), "=r"(r[1]), "=r"(r[2]), "=r"(r[3]) : "r"(a));
}
__device__ __forceinline__ void ldsm4t(uint32_t* r, uint32_t a) {
    asm volatile("ldmatrix.sync.aligned.m8n8.x4.trans.shared.b16 {%0,%1,%2,%3}, [%4];"
                 : "=r"(r[0]), "=r"(r[1]), "=r"(r[2]), "=r"(r[3]) : "r"(a));
}
__device__ __forceinline__ void mma_f16(float* d, const uint32_t* a, const uint32_t* b) {
    asm volatile("mma.sync.aligned.m16n8k16.row.col.f32.f16.f16.f32 "
                 "{%0,%1,%2,%3}, {%4,%5,%6,%7}, {%8,%9}, {%0,%1,%2,%3};"
                 : "+f"(d[0]), "+f"(d[1]), "+f"(d[2]), "+f"(d[3])
                 : "r"(a[0]), "r"(a[1]), "r"(a[2]), "r"(a[3]), "r"(b[0]), "r"(b[1]));
}
#define CP_ASYNC16(dst, src) \
    asm volatile("cp.async.cg.shared.global [%0], [%1], 16;" :: "r"(dst), "l"(src))
#define CP_COMMIT() asm volatile("cp.async.commit_group;" ::: "memory")
#define CP_WAIT1()  asm volatile("cp.async.wait_group 1;" ::: "memory")
#define CP_WAIT0()  asm volatile("cp.async.wait_group 0;" ::: "memory")

// ============== prep (merged): W1 tiles + x tiles ==============
__global__ void __launch_bounds__(256) prep_kernel(
    const float* __restrict__ W1, const float* __restrict__ x)
{
    const int bid = blockIdx.x;
    if (bid < 256) {
        // W1 -> fp16 causal-masked swizzled tiles
        const int nb = bid >> 4, ks = bid & 15;
        __half* dst = g_w1t + (nb * 16 + ks) * 2048;
        #pragma unroll
        for (int i = 0; i < 8; ++i) {
            int e = threadIdx.x + i * 256;        // 0..2047 = 16k x 128n
            int k = e >> 7, nl = e & 127;
            int l = nb * 16 + (nl >> 3), h = nl & 7;
            int kg = ks * 16 + k;
            float v = (l < LL && kg <= l) ? W1[((size_t)l * DD + kg) * HH + h] : 0.f;
            uint32_t off = (uint32_t)k * 128 + ((((nl >> 3) ^ (k & 7))) << 3) + (nl & 7);
            dst[off] = __float2half(v);
        }
    } else {
        // x -> fp16 swizzled k-chunk tiles
        int t = (bid - 256) * 256 + threadIdx.x;  // 524288 store-units of 16B
        int kg8 = t & 7;
        int r   = (t >> 3) & 127;
        int kbmb = t >> 10;
        int kb = kbmb & 3, mb = kbmb >> 2;
        const float* src = x + ((size_t)(mb * 128 + r) * DD + kb * 64 + kg8 * 8);
        float4 v0 = *(const float4*)src;
        float4 v1 = *(const float4*)(src + 4);
        __half2 h0 = __floats2half2_rn(v0.x, v0.y);
        __half2 h1 = __floats2half2_rn(v0.z, v0.w);
        __half2 h2 = __floats2half2_rn(v1.x, v1.y);
        __half2 h3 = __floats2half2_rn(v1.z, v1.w);
        uint4 pk = make_uint4(*(uint32_t*)&h0, *(uint32_t*)&h1, *(uint32_t*)&h2, *(uint32_t*)&h3);
        unsigned char* dp = (unsigned char*)g_xh + (size_t)(mb * 4 + kb) * 16384
                          + (uint32_t)r * 128 + (((uint32_t)(kg8 ^ (r & 7))) << 4);
        *(uint4*)dp = pk;
    }
}

// ============== fused GEMM + MLP + z ==============
#define ABUF_OFF 0        // 2 x 16KB
#define BBUF_OFF 32768    // 2 x 16KB
// epilogue layout (overlaps the dead A/B buffers)
#define HSTR 136          // h1 stage row stride in halves (272B, 16B aligned)
#define STG2_OFF 0        // 128 x HSTR fp16 h1  (34816B)
#define XS2_OFF  34816    // 128 x 17 fp32       (8704B)
#define ZST_OFF  43520    // 128 x 17 fp32
#define AS2_OFF  52224    // 128 x 17 fp32
#define GEMM_SMEM 65536

extern __shared__ unsigned char gsmem[];

__global__ void __launch_bounds__(256, 2) gemm_kernel(
    const float* __restrict__ x,  const float* __restrict__ b1,
    const float* __restrict__ W2, const float* __restrict__ b2,
    const float* __restrict__ W3, const float* __restrict__ b3,
    float* __restrict__ out)
{
    const int tid  = threadIdx.x;
    const int warp = tid >> 5;
    const int lane = tid & 31;
    const int wm   = warp & 3;      // M quarter (32 rows)
    const int wn   = warp >> 2;     // N half (64 cols)
    const int mb   = blockIdx.x >> 4;   // desync: adjacent bids span nb values
    const int nb   = blockIdx.x & 15;
    const int nc   = (nb >> 2) + 1; // causal: # of 64-wide k-chunks needed

    const uint32_t sb = smem_u32(gsmem);

    auto pfA = [&](int kb, int buf) {
        uint32_t dst = sb + ABUF_OFF + (uint32_t)buf * 16384 + (uint32_t)tid * 64;
        const unsigned char* src = (const unsigned char*)g_xh
            + (size_t)(mb * 4 + kb) * 16384 + (size_t)tid * 64;
        #pragma unroll
        for (int i = 0; i < 4; ++i) CP_ASYNC16(dst + i * 16, src + i * 16);
    };
    auto pfB = [&](int kb, int buf) {
        uint32_t dst = sb + BBUF_OFF + (uint32_t)buf * 16384 + (uint32_t)tid * 64;
        const unsigned char* src = (const unsigned char*)g_w1t
            + (size_t)(nb * 16 + kb * 4) * 4096 + (size_t)tid * 64;
        #pragma unroll
        for (int i = 0; i < 4; ++i) CP_ASYNC16(dst + i * 16, src + i * 16);
    };

    pfA(0, 0); pfB(0, 0); CP_COMMIT();
    if (nc > 1) { pfA(1, 1); pfB(1, 1); CP_COMMIT(); }

    float acc[2][8][4];
    #pragma unroll
    for (int mt = 0; mt < 2; ++mt)
        #pragma unroll
        for (int t = 0; t < 8; ++t)
            #pragma unroll
            for (int q = 0; q < 4; ++q) acc[mt][t][q] = 0.f;

    const int arow0 = wm * 32 + (lane & 7) + ((lane >> 3) & 1) * 8;
    const int bk    = (lane & 7) + ((lane >> 3) & 1) * 8;

    for (int kb = 0; kb < nc; ++kb) {
        if (kb < nc - 1) { CP_WAIT1(); } else { CP_WAIT0(); }
        __syncthreads();
        const uint32_t aBuf = sb + ABUF_OFF + (uint32_t)(kb & 1) * 16384;
        const uint32_t bBuf = sb + BBUF_OFF + (uint32_t)(kb & 1) * 16384;
        #pragma unroll
        for (int kt = 0; kt < 4; ++kt) {
            uint32_t af[2][4], bf[4][4];
            uint32_t g = (uint32_t)(2 * kt + (lane >> 4));
            uint32_t offk = ((g ^ (uint32_t)(arow0 & 7)) << 4);
            ldsm4(af[0], aBuf + (uint32_t)arow0 * 128 + offk);
            uint32_t offk1 = ((g ^ (uint32_t)((arow0 + 16) & 7)) << 4);
            ldsm4(af[1], aBuf + (uint32_t)(arow0 + 16) * 128 + offk1);
            #pragma unroll
            for (int p = 0; p < 4; ++p) {
                uint32_t cidx = (uint32_t)(wn * 8 + 2 * p + (lane >> 4));
                ldsm4t(bf[p], bBuf + (uint32_t)kt * 4096 + (uint32_t)bk * 256
                              + ((cidx ^ (uint32_t)(lane & 7)) << 4));
            }
            #pragma unroll
            for (int mt = 0; mt < 2; ++mt)
                #pragma unroll
                for (int p = 0; p < 4; ++p) {
                    mma_f16(acc[mt][2 * p],     af[mt], &bf[p][0]);
                    mma_f16(acc[mt][2 * p + 1], af[mt], &bf[p][2]);
                }
        }
        __syncthreads();
        if (kb + 2 < nc) { pfA(kb + 2, kb & 1); pfB(kb + 2, kb & 1); CP_COMMIT(); }
    }
    // after the loop's trailing __syncthreads, A/B buffers are dead -> reuse as stg

    __half* stg = (__half*)(gsmem + STG2_OFF);  // [128][HSTR] fp16 h1
    float* xs  = (float*)(gsmem + XS2_OFF);     // [128][17]
    float* zst = (float*)(gsmem + ZST_OFF);     // [128][17]
    float* as2 = (float*)(gsmem + AS2_OFF);     // [128][17]

    // ---- stage h1 = tanh(acc + b1) as fp16 (fragment -> smem) ----
    {
        const int h  = (lane & 3) * 2;
        const int r0 = wm * 32 + (lane >> 2);
        #pragma unroll
        for (int t = 0; t < 8; ++t) {
            int l = nb * 16 + wn * 8 + t;
            float2 b1v = make_float2(0.f, 0.f);
            if (l < LL) b1v = *(const float2*)(b1 + l * 8 + h);
            int ln = (wn * 8 + t) * 8 + h;
            #pragma unroll
            for (int mt = 0; mt < 2; ++mt) {
                __half2 p01 = __floats2half2_rn(ftanha(acc[mt][t][0] + b1v.x),
                                                ftanha(acc[mt][t][1] + b1v.y));
                *(__half2*)(stg + (r0 + mt * 16) * HSTR + ln) = p01;
                __half2 p23 = __floats2half2_rn(ftanha(acc[mt][t][2] + b1v.x),
                                                ftanha(acc[mt][t][3] + b1v.y));
                *(__half2*)(stg + (r0 + mt * 16 + 8) * HSTR + ln) = p23;
            }
        }
    }
    // ---- stage x columns nb*16+1 .. nb*16+16 ----
    #pragma unroll
    for (int i = 0; i < 8; ++i) {
        int v = tid + i * 256;
        int r = v >> 4, cc = v & 15;
        int col = nb * 16 + 1 + cc;
        xs[r * 17 + cc] = (col < DD) ? x[(size_t)(mb * 128 + r) * DD + col] : 0.f;
    }

    // ---- MLP weights -> registers BEFORE the barrier (latency hides in barrier) ----
    const int jl   = tid >> 4;          // 0..15
    const int slot = tid & 15;
    const int l    = nb * 16 + jl;
    const bool act = (l < LL);
    const int lw   = act ? l : 0;

    unsigned long long w2u[32];
    {
        const float4* w2p = (const float4*)(W2 + lw * 64);
        #pragma unroll
        for (int i = 0; i < 16; ++i) {
            float4 v = w2p[i];
            w2u[2 * i]     = pk2(v.x, v.y);
            w2u[2 * i + 1] = pk2(v.z, v.w);
        }
    }
    float4 w3r[4];
    {
        const float4* w3p = (const float4*)(W3 + lw * 16);
        #pragma unroll
        for (int i = 0; i < 4; ++i) w3r[i] = w3p[i];
    }
    unsigned long long b2p[4];
    {
        float4 a = ((const float4*)(b2 + lw * 8))[0];
        float4 b = ((const float4*)(b2 + lw * 8))[1];
        b2p[0] = pk2(a.x, a.y); b2p[1] = pk2(a.z, a.w);
        b2p[2] = pk2(b.x, b.y); b2p[3] = pk2(b.z, b.w);
    }
    float2 b3v = *(const float2*)(b3 + lw * 2);

    __syncthreads();

    // ---- MLP jobs: thread = (layer-lane jl, slot), 8 rows each ----
    #pragma unroll
    for (int i = 0; i < 8; ++i) {
        int row = slot + 16 * i;
        if (act) {
            uint4 q = *(const uint4*)(stg + row * HSTR + jl * 8);  // 8 halves
            float2 f0 = __half22float2(*(__half2*)&q.x);
            float2 f1 = __half22float2(*(__half2*)&q.y);
            float2 f2 = __half22float2(*(__half2*)&q.z);
            float2 f3 = __half22float2(*(__half2*)&q.w);
            float h1v[8] = {f0.x, f0.y, f1.x, f1.y, f2.x, f2.y, f3.x, f3.y};

            unsigned long long a2[4] = {b2p[0], b2p[1], b2p[2], b2p[3]};
            #pragma unroll
            for (int hh = 0; hh < 8; ++hh) {
                unsigned long long hp = pk2(h1v[hh], h1v[hh]);
                fma2(a2[0], hp, w2u[hh * 4 + 0]);
                fma2(a2[1], hp, w2u[hh * 4 + 1]);
                fma2(a2[2], hp, w2u[hh * 4 + 2]);
                fma2(a2[3], hp, w2u[hh * 4 + 3]);
            }
            float mu = b3v.x, al = b3v.y;
            #pragma unroll
            for (int qq = 0; qq < 4; ++qq) {
                float2 pr = up2(a2[qq]);
                float h2a = ftanha(pr.x), h2b = ftanha(pr.y);
                mu += h2a * w3r[qq].x + h2b * w3r[qq].z;
                al += h2a * w3r[qq].y + h2b * w3r[qq].w;
            }
            float xn = xs[row * 17 + jl];
            zst[row * 17 + jl] = (xn - mu) * __expf(-al);
            as2[row * 17 + jl] = al;
        } else {
            as2[row * 17 + jl] = 0.f;
        }
    }
    __syncthreads();

    // ---- flush z (coalesced, reversed) + alpha partial ----
    #pragma unroll
    for (int it = 0; it < 8; ++it) {
        int v = tid + it * 256;
        int r = v >> 4, cc = v & 15;
        int col = 239 - nb * 16 + cc;
        if (col >= 0)
            out[(size_t)(mb * 128 + r) * DD + col] = zst[r * 17 + (15 - cc)];
    }
    if (tid < 128) {
        float s = 0.f;
        #pragma unroll
        for (int q = 0; q < 16; ++q) s += as2[tid * 17 + q];
        g_apart[nb * BB + mb * 128 + tid] = s;
    }
}

// ============== final: col 255 + log_det (deterministic 16-way sum) ==============
__global__ void __launch_bounds__(512) zfinal_kernel(
    const float* __restrict__ x, const float* __restrict__ ipar,
    float* __restrict__ out, int out_size)
{
    int r = blockIdx.x * 512 + threadIdx.x;
    float s = 0.f;
    #pragma unroll
    for (int nb = 0; nb < 16; ++nb) s += g_apart[nb * BB + r];
    float ip0 = ipar[0], ip1 = ipar[1];
    out[(size_t)r * DD + 255] = (x[(size_t)r * DD] - ip0) * __expf(-ip1);
    if (out_size > BB * DD)
        out[(size_t)BB * DD + r] = -(ip1 + s);
}

extern "C" void kernel_launch(void* const* d_in, const int* in_sizes, int n_in,
                              void* d_out, int out_size)
{
    const float* x    = (const float*)d_in[0];
    const float* ipar = (const float*)d_in[1];
    const float* W1   = (const float*)d_in[2];
    const float* b1   = (const float*)d_in[3];
    const float* W2   = (const float*)d_in[4];
    const float* b2   = (const float*)d_in[5];
    const float* W3   = (const float*)d_in[6];
    const float* b3   = (const float*)d_in[7];
    float* out = (float*)d_out;

    prep_kernel<<<256 + 2048, 256>>>(W1, x);
    cudaFuncSetAttribute(gemm_kernel, cudaFuncAttributeMaxDynamicSharedMemorySize, GEMM_SMEM);
    gemm_kernel<<<2048, 256, GEMM_SMEM>>>(x, b1, W2, b2, W3, b3, out);
    zfinal_kernel<<<BB / 512, 512>>>(x, ipar, out, out_size);
}

// round 16
// speedup vs baseline: 2.7959x; 1.0352x over previous
#include <cuda_runtime.h>
#include <cuda_fp16.h>
#include <cstdint>
#include <cstddef>

// Problem constants
#define BB 16384
#define DD 256
#define LL 255
#define HH 8

// ---- device scratch ----
__device__ __align__(16) __half g_w1t[16 * 16 * 2048];
__device__ __align__(16) __half g_xh[128 * 4 * 8192];
__device__ __align__(16) float  g_apart[16 * BB];   // per-nb alpha partials
// W2 layer-pair B fragments, pre-packed in m16n8k16 register layout (hi/lo split)
__device__ __align__(16) uint4  g_w2f [128 * 32];
__device__ __align__(16) uint4  g_w2fl[128 * 32];

// ============================ helpers ============================
__device__ __forceinline__ uint32_t smem_u32(const void* p) {
    uint32_t a;
    asm("{ .reg .u64 t; cvta.to.shared.u64 t, %1; cvt.u32.u64 %0, t; }" : "=r"(a) : "l"(p));
    return a;
}
__device__ __forceinline__ float ftanha(float v) {
    float r;
    asm("tanh.approx.f32 %0, %1;" : "=f"(r) : "f"(v));
    return r;
}
__device__ __forceinline__ void ldsm4(uint32_t* r, uint32_t a) {
    asm volatile("ldmatrix.sync.aligned.m8n8.x4.shared.b16 {%0,%1,%2,%3}, [%4];"
                 : "=r"(r[0]), "=r"(r[1]), "=r"(r[2]), "=r"(r[3]) : "r"(a));
}
__device__ __forceinline__ void ldsm4t(uint32_t* r, uint32_t a) {
    asm volatile("ldmatrix.sync.aligned.m8n8.x4.trans.shared.b16 {%0,%1,%2,%3}, [%4];"
                 : "=r"(r[0]), "=r"(r[1]), "=r"(r[2]), "=r"(r[3]) : "r"(a));
}
__device__ __forceinline__ void mma_f16(float* d, const uint32_t* a, const uint32_t* b) {
    asm volatile("mma.sync.aligned.m16n8k16.row.col.f32.f16.f16.f32 "
                 "{%0,%1,%2,%3}, {%4,%5,%6,%7}, {%8,%9}, {%0,%1,%2,%3};"
                 : "+f"(d[0]), "+f"(d[1]), "+f"(d[2]), "+f"(d[3])
                 : "r"(a[0]), "r"(a[1]), "r"(a[2]), "r"(a[3]), "r"(b[0]), "r"(b[1]));
}
__device__ __forceinline__ uint32_t pack_hh(float a, float b) {
    __half2 h = __floats2half2_rn(a, b);
    return *(uint32_t*)&h;
}
#define CP_ASYNC16(dst, src) \
    asm volatile("cp.async.cg.shared.global [%0], [%1], 16;" :: "r"(dst), "l"(src))
#define CP_COMMIT() asm volatile("cp.async.commit_group;" ::: "memory")
#define CP_WAIT1()  asm volatile("cp.async.wait_group 1;" ::: "memory")
#define CP_WAIT0()  asm volatile("cp.async.wait_group 0;" ::: "memory")

// ============== prep (merged): W1 tiles + x tiles + W2 fragments ==============
__global__ void __launch_bounds__(256) prep_kernel(
    const float* __restrict__ W1, const float* __restrict__ x,
    const float* __restrict__ W2)
{
    const int bid = blockIdx.x;
    if (bid < 256) {
        // W1 -> fp16 causal-masked swizzled tiles
        const int nb = bid >> 4, ks = bid & 15;
        __half* dst = g_w1t + (nb * 16 + ks) * 2048;
        #pragma unroll
        for (int i = 0; i < 8; ++i) {
            int e = threadIdx.x + i * 256;        // 0..2047 = 16k x 128n
            int k = e >> 7, nl = e & 127;
            int l = nb * 16 + (nl >> 3), h = nl & 7;
            int kg = ks * 16 + k;
            float v = (l < LL && kg <= l) ? W1[((size_t)l * DD + kg) * HH + h] : 0.f;
            uint32_t off = (uint32_t)k * 128 + ((((nl >> 3) ^ (k & 7))) << 3) + (nl & 7);
            dst[off] = __float2half(v);
        }
    } else if (bid < 2304) {
        // x -> fp16 swizzled k-chunk tiles
        int t = (bid - 256) * 256 + threadIdx.x;  // 524288 store-units of 16B
        int kg8 = t & 7;
        int r   = (t >> 3) & 127;
        int kbmb = t >> 10;
        int kb = kbmb & 3, mb = kbmb >> 2;
        const float* src = x + ((size_t)(mb * 128 + r) * DD + kb * 64 + kg8 * 8);
        float4 v0 = *(const float4*)src;
        float4 v1 = *(const float4*)(src + 4);
        __half2 h0 = __floats2half2_rn(v0.x, v0.y);
        __half2 h1 = __floats2half2_rn(v0.z, v0.w);
        __half2 h2 = __floats2half2_rn(v1.x, v1.y);
        __half2 h3 = __floats2half2_rn(v1.z, v1.w);
        uint4 pk = make_uint4(*(uint32_t*)&h0, *(uint32_t*)&h1, *(uint32_t*)&h2, *(uint32_t*)&h3);
        unsigned char* dp = (unsigned char*)g_xh + (size_t)(mb * 4 + kb) * 16384
                          + (uint32_t)r * 128 + (((uint32_t)(kg8 ^ (r & 7))) << 4);
        *(uint4*)dp = pk;
    } else {
        // W2 layer-pair block-diag B fragments (hi/lo)
        int blk = bid - 2304;                 // 0..15
        int jl = threadIdx.x >> 5, lane = threadIdx.x & 31;
        int j = blk * 8 + jl;                 // 0..127 (layers 2j, 2j+1)
        auto bval = [&](int k, int n) -> float {
            int bk = k >> 3, bn = n >> 3;
            if (bk != bn) return 0.f;
            int l = 2 * j + bk;
            if (l >= LL) return 0.f;
            return W2[(l * 8 + (k & 7)) * 8 + (n & 7)];
        };
        uint32_t hi[4], lo[4];
        #pragma unroll
        for (int q = 0; q < 4; ++q) {
            int k = 2 * (lane & 3) + ((q & 1) ? 8 : 0);
            int n = (lane >> 2) + ((q & 2) ? 8 : 0);
            float v0 = bval(k, n), v1 = bval(k + 1, n);
            __half h0 = __float2half(v0), h1 = __float2half(v1);
            float r0 = v0 - __half2float(h0), r1 = v1 - __half2float(h1);
            hi[q] = (uint32_t)(*(uint16_t*)&h0) | ((uint32_t)(*(uint16_t*)&h1) << 16);
            __half l0 = __float2half(r0), l1 = __float2half(r1);
            lo[q] = (uint32_t)(*(uint16_t*)&l0) | ((uint32_t)(*(uint16_t*)&l1) << 16);
        }
        g_w2f [j * 32 + lane] = make_uint4(hi[0], hi[1], hi[2], hi[3]);
        g_w2fl[j * 32 + lane] = make_uint4(lo[0], lo[1], lo[2], lo[3]);
    }
}

// ============== fused GEMM + MLP + z ==============
#define ABUF_OFF 0        // 2 x 16KB  (later: h1a swizzled fp16 128x128)
#define BBUF_OFF 32768    // 2 x 16KB  (later: h2s)
#define HSTR 136          // h2 stage row stride in halves
#define H2S_OFF  32768    // 128 x HSTR fp16 (34816B, ends 67584)
#define XS2_OFF  67584    // 128 x 17 fp32
#define ZST_OFF  76288    // 128 x 17 fp32
#define AS2_OFF  84992    // 128 x 17 fp32
#define GEMM_SMEM 93696

extern __shared__ unsigned char gsmem[];

__global__ void __launch_bounds__(256, 2) gemm_kernel(
    const float* __restrict__ x,  const float* __restrict__ b1,
    const float* __restrict__ b2,
    const float* __restrict__ W3, const float* __restrict__ b3,
    float* __restrict__ out)
{
    const int tid  = threadIdx.x;
    const int warp = tid >> 5;
    const int lane = tid & 31;
    const int wm   = warp & 3;      // M quarter (32 rows)
    const int wn   = warp >> 2;     // N half (64 cols)
    const int mb   = blockIdx.x >> 4;   // desync: adjacent bids span nb
    const int nb   = blockIdx.x & 15;
    const int nc   = (nb >> 2) + 1;

    const uint32_t sb = smem_u32(gsmem);

    auto pfA = [&](int kb, int buf) {
        uint32_t dst = sb + ABUF_OFF + (uint32_t)buf * 16384 + (uint32_t)tid * 64;
        const unsigned char* src = (const unsigned char*)g_xh
            + (size_t)(mb * 4 + kb) * 16384 + (size_t)tid * 64;
        #pragma unroll
        for (int i = 0; i < 4; ++i) CP_ASYNC16(dst + i * 16, src + i * 16);
    };
    auto pfB = [&](int kb, int buf) {
        uint32_t dst = sb + BBUF_OFF + (uint32_t)buf * 16384 + (uint32_t)tid * 64;
        const unsigned char* src = (const unsigned char*)g_w1t
            + (size_t)(nb * 16 + kb * 4) * 4096 + (size_t)tid * 64;
        #pragma unroll
        for (int i = 0; i < 4; ++i) CP_ASYNC16(dst + i * 16, src + i * 16);
    };

    pfA(0, 0); pfB(0, 0); CP_COMMIT();
    if (nc > 1) { pfA(1, 1); pfB(1, 1); CP_COMMIT(); }

    float acc[2][8][4];
    #pragma unroll
    for (int mt = 0; mt < 2; ++mt)
        #pragma unroll
        for (int t = 0; t < 8; ++t)
            #pragma unroll
            for (int q = 0; q < 4; ++q) acc[mt][t][q] = 0.f;

    const int arow0 = wm * 32 + (lane & 7) + ((lane >> 3) & 1) * 8;
    const int bk    = (lane & 7) + ((lane >> 3) & 1) * 8;

    for (int kb = 0; kb < nc; ++kb) {
        if (kb < nc - 1) { CP_WAIT1(); } else { CP_WAIT0(); }
        __syncthreads();
        const uint32_t aBuf = sb + ABUF_OFF + (uint32_t)(kb & 1) * 16384;
        const uint32_t bBuf = sb + BBUF_OFF + (uint32_t)(kb & 1) * 16384;
        #pragma unroll
        for (int kt = 0; kt < 4; ++kt) {
            uint32_t af[2][4], bf[4][4];
            uint32_t g = (uint32_t)(2 * kt + (lane >> 4));
            uint32_t offk = ((g ^ (uint32_t)(arow0 & 7)) << 4);
            ldsm4(af[0], aBuf + (uint32_t)arow0 * 128 + offk);
            uint32_t offk1 = ((g ^ (uint32_t)((arow0 + 16) & 7)) << 4);
            ldsm4(af[1], aBuf + (uint32_t)(arow0 + 16) * 128 + offk1);
            #pragma unroll
            for (int p = 0; p < 4; ++p) {
                uint32_t cidx = (uint32_t)(wn * 8 + 2 * p + (lane >> 4));
                ldsm4t(bf[p], bBuf + (uint32_t)kt * 4096 + (uint32_t)bk * 256
                              + ((cidx ^ (uint32_t)(lane & 7)) << 4));
            }
            #pragma unroll
            for (int mt = 0; mt < 2; ++mt)
                #pragma unroll
                for (int p = 0; p < 4; ++p) {
                    mma_f16(acc[mt][2 * p],     af[mt], &bf[p][0]);
                    mma_f16(acc[mt][2 * p + 1], af[mt], &bf[p][2]);
                }
        }
        __syncthreads();
        if (kb + 2 < nc) { pfA(kb + 2, kb & 1); pfB(kb + 2, kb & 1); CP_COMMIT(); }
    }
    // A/B buffers dead now.

    __half* h2s = (__half*)(gsmem + H2S_OFF);
    float* xs  = (float*)(gsmem + XS2_OFF);
    float* zst = (float*)(gsmem + ZST_OFF);
    float* as2 = (float*)(gsmem + AS2_OFF);

    // ---- stage h1 = tanh(acc + b1) fp16 into swizzled A-tile format (ABUF) ----
    {
        const int h  = (lane & 3) * 2;
        const int rq = lane >> 2;             // row&7 for both r and r+8
        const int r0 = wm * 32 + rq;
        #pragma unroll
        for (int t = 0; t < 8; ++t) {
            int l = nb * 16 + wn * 8 + t;
            float2 b1v = make_float2(0.f, 0.f);
            if (l < LL) b1v = *(const float2*)(b1 + l * 8 + h);
            int lcol = (wn * 8 + t) * 8 + h;  // global k col 0..127
            uint32_t base = (uint32_t)(lcol >> 6) * 16384
                          + (((uint32_t)((lcol & 63) >> 3) ^ (uint32_t)(rq & 7)) << 4)
                          + (uint32_t)((lcol & 7) * 2);
            #pragma unroll
            for (int mt = 0; mt < 2; ++mt) {
                uint32_t a0 = base + (uint32_t)(r0 + mt * 16) * 128;
                *(uint32_t*)(gsmem + a0) =
                    pack_hh(ftanha(acc[mt][t][0] + b1v.x), ftanha(acc[mt][t][1] + b1v.y));
                *(uint32_t*)(gsmem + a0 + 8 * 128) =
                    pack_hh(ftanha(acc[mt][t][2] + b1v.x), ftanha(acc[mt][t][3] + b1v.y));
            }
        }
    }
    // ---- stage x columns nb*16+1 .. nb*16+16 ----
    #pragma unroll
    for (int i = 0; i < 8; ++i) {
        int v = tid + i * 256;
        int r = v >> 4, cc = v & 15;
        int col = nb * 16 + 1 + cc;
        xs[r * 17 + cc] = (col < DD) ? x[(size_t)(mb * 128 + r) * DD + col] : 0.f;
    }

    // ---- pre-barrier loads: W2 fragments, b2, layer-3 weights ----
    const int w = warp;                      // layer pair j = nb*8 + w
    uint4 bh4 = g_w2f [(nb * 8 + w) * 32 + lane];
    uint4 bl4 = g_w2fl[(nb * 8 + w) * 32 + lane];
    float2 b2v[2];
    #pragma unroll
    for (int nt = 0; nt < 2; ++nt) {
        int l = nb * 16 + 2 * w + nt;
        b2v[nt] = (l < LL) ? *(const float2*)(b2 + l * 8 + (lane & 3) * 2)
                           : make_float2(0.f, 0.f);
    }
    const int jl   = tid >> 4;               // 0..15 (job layer lane)
    const int slot = tid & 15;
    const int lj   = nb * 16 + jl;
    const bool act = (lj < LL);
    const int lw   = act ? lj : 0;
    float4 w3r[4];
    {
        const float4* w3p = (const float4*)(W3 + lw * 16);
        #pragma unroll
        for (int i = 0; i < 4; ++i) w3r[i] = w3p[i];
    }
    float2 b3v = *(const float2*)(b3 + lw * 2);

    __syncthreads();   // h1a visible

    // ---- MMA2: layer 2 (block-diag, hi/lo split) ----
    {
        float acc2[8][2][4];
        #pragma unroll
        for (int mt = 0; mt < 8; ++mt)
            #pragma unroll
            for (int nt = 0; nt < 2; ++nt)
                #pragma unroll
                for (int q = 0; q < 4; ++q) acc2[mt][nt][q] = 0.f;

        const int ar = (lane & 7) + ((lane >> 3) & 1) * 8;
        const uint32_t gg = (uint32_t)(2 * (w & 3) + (lane >> 4));
        const uint32_t ck = (uint32_t)(w >> 2) * 16384;
        #pragma unroll
        for (int mt = 0; mt < 8; ++mt) {
            uint32_t af[4];
            uint32_t row = (uint32_t)(mt * 16 + ar);
            ldsm4(af, sb + ck + row * 128 + ((gg ^ (row & 7)) << 4));
            mma_f16(acc2[mt][0], af, (const uint32_t*)&bh4);
            mma_f16(acc2[mt][0], af, (const uint32_t*)&bl4);
            mma_f16(acc2[mt][1], af, ((const uint32_t*)&bh4) + 2);
            mma_f16(acc2[mt][1], af, ((const uint32_t*)&bl4) + 2);
        }
        // h2 = tanh(acc2 + b2) -> fp16 staging
        const int rq = lane >> 2;
        const int c0 = w * 16 + (lane & 3) * 2;
        #pragma unroll
        for (int mt = 0; mt < 8; ++mt) {
            int r = mt * 16 + rq;
            #pragma unroll
            for (int nt = 0; nt < 2; ++nt) {
                *(uint32_t*)(h2s + r * HSTR + c0 + nt * 8) =
                    pack_hh(ftanha(acc2[mt][nt][0] + b2v[nt].x),
                            ftanha(acc2[mt][nt][1] + b2v[nt].y));
                *(uint32_t*)(h2s + (r + 8) * HSTR + c0 + nt * 8) =
                    pack_hh(ftanha(acc2[mt][nt][2] + b2v[nt].x),
                            ftanha(acc2[mt][nt][3] + b2v[nt].y));
            }
        }
    }
    __syncthreads();   // h2s visible

    // ---- jobs: layer 3 only, 8 rows per thread ----
    #pragma unroll
    for (int i = 0; i < 8; ++i) {
        int row = slot + 16 * i;
        if (act) {
            uint4 q = *(const uint4*)(h2s + row * HSTR + jl * 8);
            float2 f0 = __half22float2(*(__half2*)&q.x);
            float2 f1 = __half22float2(*(__half2*)&q.y);
            float2 f2 = __half22float2(*(__half2*)&q.z);
            float2 f3 = __half22float2(*(__half2*)&q.w);
            float mu = b3v.x, al = b3v.y;
            mu += f0.x * w3r[0].x + f0.y * w3r[0].z;
            al += f0.x * w3r[0].y + f0.y * w3r[0].w;
            mu += f1.x * w3r[1].x + f1.y * w3r[1].z;
            al += f1.x * w3r[1].y + f1.y * w3r[1].w;
            mu += f2.x * w3r[2].x + f2.y * w3r[2].z;
            al += f2.x * w3r[2].y + f2.y * w3r[2].w;
            mu += f3.x * w3r[3].x + f3.y * w3r[3].z;
            al += f3.x * w3r[3].y + f3.y * w3r[3].w;
            float xn = xs[row * 17 + jl];
            zst[row * 17 + jl] = (xn - mu) * __expf(-al);
            as2[row * 17 + jl] = al;
        } else {
            as2[row * 17 + jl] = 0.f;
        }
    }
    __syncthreads();

    // ---- flush z (coalesced, reversed) + alpha partial ----
    #pragma unroll
    for (int it = 0; it < 8; ++it) {
        int v = tid + it * 256;
        int r = v >> 4, cc = v & 15;
        int col = 239 - nb * 16 + cc;
        if (col >= 0)
            out[(size_t)(mb * 128 + r) * DD + col] = zst[r * 17 + (15 - cc)];
    }
    if (tid < 128) {
        float s = 0.f;
        #pragma unroll
        for (int q = 0; q < 16; ++q) s += as2[tid * 17 + q];
        g_apart[nb * BB + mb * 128 + tid] = s;
    }
}

// ============== final: col 255 + log_det ==============
__global__ void __launch_bounds__(128) zfinal_kernel(
    const float* __restrict__ x, const float* __restrict__ ipar,
    float* __restrict__ out, int out_size)
{
    int r = blockIdx.x * 128 + threadIdx.x;
    float s = 0.f;
    #pragma unroll
    for (int nb = 0; nb < 16; ++nb) s += g_apart[nb * BB + r];
    float ip0 = ipar[0], ip1 = ipar[1];
    out[(size_t)r * DD + 255] = (x[(size_t)r * DD] - ip0) * __expf(-ip1);
    if (out_size > BB * DD)
        out[(size_t)BB * DD + r] = -(ip1 + s);
}

extern "C" void kernel_launch(void* const* d_in, const int* in_sizes, int n_in,
                              void* d_out, int out_size)
{
    const float* x    = (const float*)d_in[0];
    const float* ipar = (const float*)d_in[1];
    const float* W1   = (const float*)d_in[2];
    const float* b1   = (const float*)d_in[3];
    const float* W2   = (const float*)d_in[4];
    const float* b2   = (const float*)d_in[5];
    const float* W3   = (const float*)d_in[6];
    const float* b3   = (const float*)d_in[7];
    float* out = (float*)d_out;

    prep_kernel<<<2320, 256>>>(W1, x, W2);
    cudaFuncSetAttribute(gemm_kernel, cudaFuncAttributeMaxDynamicSharedMemorySize, GEMM_SMEM);
    gemm_kernel<<<2048, 256, GEMM_SMEM>>>(x, b1, b2, W3, b3, out);
    zfinal_kernel<<<BB / 128, 128>>>(x, ipar, out, out_size);
}

// round 17
// speedup vs baseline: 2.8254x; 1.0105x over previous
#include <cuda_runtime.h>
#include <cuda_fp16.h>
#include <cstdint>
#include <cstddef>

// Problem constants
#define BB 16384
#define DD 256
#define LL 255
#define HH 8

// ---- device scratch ----
__device__ __align__(16) __half g_w1t[16 * 16 * 2048];
__device__ __align__(16) __half g_xh[128 * 4 * 8192];
__device__ __align__(16) float  g_apart[16 * BB];   // per-nb alpha partials
// W2 layer-pair B fragments (m16n8k16 layout, hi/lo split)
__device__ __align__(16) uint4  g_w2f [128 * 32];
__device__ __align__(16) uint4  g_w2fl[128 * 32];
// W3 block-diag B fragments: [nb][kt][lane] = {b0hi,b1hi,b0lo,b1lo}
__device__ __align__(16) uint4  g_w3f [16 * 8 * 32];

// ============================ helpers ============================
__device__ __forceinline__ uint32_t smem_u32(const void* p) {
    uint32_t a;
    asm("{ .reg .u64 t; cvta.to.shared.u64 t, %1; cvt.u32.u64 %0, t; }" : "=r"(a) : "l"(p));
    return a;
}
__device__ __forceinline__ float ftanha(float v) {
    float r;
    asm("tanh.approx.f32 %0, %1;" : "=f"(r) : "f"(v));
    return r;
}
__device__ __forceinline__ void ldsm4(uint32_t* r, uint32_t a) {
    asm volatile("ldmatrix.sync.aligned.m8n8.x4.shared.b16 {%0,%1,%2,%3}, [%4];"
                 : "=r"(r[0]), "=r"(r[1]), "=r"(r[2]), "=r"(r[3]) : "r"(a));
}
__device__ __forceinline__ void ldsm4t(uint32_t* r, uint32_t a) {
    asm volatile("ldmatrix.sync.aligned.m8n8.x4.trans.shared.b16 {%0,%1,%2,%3}, [%4];"
                 : "=r"(r[0]), "=r"(r[1]), "=r"(r[2]), "=r"(r[3]) : "r"(a));
}
__device__ __forceinline__ void mma_f16(float* d, const uint32_t* a, const uint32_t* b) {
    asm volatile("mma.sync.aligned.m16n8k16.row.col.f32.f16.f16.f32 "
                 "{%0,%1,%2,%3}, {%4,%5,%6,%7}, {%8,%9}, {%0,%1,%2,%3};"
                 : "+f"(d[0]), "+f"(d[1]), "+f"(d[2]), "+f"(d[3])
                 : "r"(a[0]), "r"(a[1]), "r"(a[2]), "r"(a[3]), "r"(b[0]), "r"(b[1]));
}
__device__ __forceinline__ uint32_t pack_hh(float a, float b) {
    __half2 h = __floats2half2_rn(a, b);
    return *(uint32_t*)&h;
}
#define CP_ASYNC16(dst, src) \
    asm volatile("cp.async.cg.shared.global [%0], [%1], 16;" :: "r"(dst), "l"(src))
#define CP_COMMIT() asm volatile("cp.async.commit_group;" ::: "memory")
#define CP_WAIT1()  asm volatile("cp.async.wait_group 1;" ::: "memory")
#define CP_WAIT0()  asm volatile("cp.async.wait_group 0;" ::: "memory")

// ============== prep: W1 tiles + x tiles + W2 frags + W3 frags ==============
__global__ void __launch_bounds__(256) prep_kernel(
    const float* __restrict__ W1, const float* __restrict__ x,
    const float* __restrict__ W2, const float* __restrict__ W3)
{
    const int bid = blockIdx.x;
    if (bid < 256) {
        // W1 -> fp16 causal-masked swizzled tiles
        const int nb = bid >> 4, ks = bid & 15;
        __half* dst = g_w1t + (nb * 16 + ks) * 2048;
        #pragma unroll
        for (int i = 0; i < 8; ++i) {
            int e = threadIdx.x + i * 256;
            int k = e >> 7, nl = e & 127;
            int l = nb * 16 + (nl >> 3), h = nl & 7;
            int kg = ks * 16 + k;
            float v = (l < LL && kg <= l) ? W1[((size_t)l * DD + kg) * HH + h] : 0.f;
            uint32_t off = (uint32_t)k * 128 + ((((nl >> 3) ^ (k & 7))) << 3) + (nl & 7);
            dst[off] = __float2half(v);
        }
    } else if (bid < 2304) {
        // x -> fp16 swizzled k-chunk tiles
        int t = (bid - 256) * 256 + threadIdx.x;
        int kg8 = t & 7;
        int r   = (t >> 3) & 127;
        int kbmb = t >> 10;
        int kb = kbmb & 3, mb = kbmb >> 2;
        const float* src = x + ((size_t)(mb * 128 + r) * DD + kb * 64 + kg8 * 8);
        float4 v0 = *(const float4*)src;
        float4 v1 = *(const float4*)(src + 4);
        __half2 h0 = __floats2half2_rn(v0.x, v0.y);
        __half2 h1 = __floats2half2_rn(v0.z, v0.w);
        __half2 h2 = __floats2half2_rn(v1.x, v1.y);
        __half2 h3 = __floats2half2_rn(v1.z, v1.w);
        uint4 pk = make_uint4(*(uint32_t*)&h0, *(uint32_t*)&h1, *(uint32_t*)&h2, *(uint32_t*)&h3);
        unsigned char* dp = (unsigned char*)g_xh + (size_t)(mb * 4 + kb) * 16384
                          + (uint32_t)r * 128 + (((uint32_t)(kg8 ^ (r & 7))) << 4);
        *(uint4*)dp = pk;
    } else if (bid < 2320) {
        // W2 layer-pair block-diag B fragments (hi/lo)
        int blk = bid - 2304;
        int jl = threadIdx.x >> 5, lane = threadIdx.x & 31;
        int j = blk * 8 + jl;
        auto bval = [&](int k, int n) -> float {
            int bk = k >> 3, bn = n >> 3;
            if (bk != bn) return 0.f;
            int l = 2 * j + bk;
            if (l >= LL) return 0.f;
            return W2[(l * 8 + (k & 7)) * 8 + (n & 7)];
        };
        uint32_t hi[4], lo[4];
        #pragma unroll
        for (int q = 0; q < 4; ++q) {
            int k = 2 * (lane & 3) + ((q & 1) ? 8 : 0);
            int n = (lane >> 2) + ((q & 2) ? 8 : 0);
            float v0 = bval(k, n), v1 = bval(k + 1, n);
            __half h0 = __float2half(v0), h1 = __float2half(v1);
            float r0 = v0 - __half2float(h0), r1 = v1 - __half2float(h1);
            hi[q] = (uint32_t)(*(uint16_t*)&h0) | ((uint32_t)(*(uint16_t*)&h1) << 16);
            __half l0 = __float2half(r0), l1 = __float2half(r1);
            lo[q] = (uint32_t)(*(uint16_t*)&l0) | ((uint32_t)(*(uint16_t*)&l1) << 16);
        }
        g_w2f [j * 32 + lane] = make_uint4(hi[0], hi[1], hi[2], hi[3]);
        g_w2fl[j * 32 + lane] = make_uint4(lo[0], lo[1], lo[2], lo[3]);
    } else {
        // W3 block-diag B fragments: per nb, per kt, nonzero n-tile = kt>>1
        int nb = bid - 2320;                  // 0..15
        int kt = threadIdx.x >> 5, lane = threadIdx.x & 31;
        auto b3val = [&](int kk, int n) -> float {   // kk 0..15 within kt, n global 0..31
            int lk = 2 * kt + (kk >> 3);      // layer (local) of this k row
            if ((n >> 1) != lk) return 0.f;
            int l = nb * 16 + lk;
            if (l >= LL) return 0.f;
            return W3[l * 16 + (kk & 7) * 2 + (n & 1)];
        };
        int n = 8 * (kt >> 1) + (lane >> 2);  // global col
        uint32_t hi[2], lo[2];
        #pragma unroll
        for (int q = 0; q < 2; ++q) {
            int kk = 2 * (lane & 3) + q * 8;
            float v0 = b3val(kk, n), v1 = b3val(kk + 1, n);
            __half h0 = __float2half(v0), h1 = __float2half(v1);
            float r0 = v0 - __half2float(h0), r1 = v1 - __half2float(h1);
            hi[q] = (uint32_t)(*(uint16_t*)&h0) | ((uint32_t)(*(uint16_t*)&h1) << 16);
            __half l0 = __float2half(r0), l1 = __float2half(r1);
            lo[q] = (uint32_t)(*(uint16_t*)&l0) | ((uint32_t)(*(uint16_t*)&l1) << 16);
        }
        g_w3f[(nb * 8 + kt) * 32 + lane] = make_uint4(hi[0], hi[1], lo[0], lo[1]);
    }
}

// ============== fused GEMM + MLP + z ==============
#define ABUF_OFF 0        // 2 x 16KB  (later: h1a swizzled fp16 128x128)
#define BBUF_OFF 32768    // 2 x 16KB  (later: h2a swizzled fp16 128x128)
#define XS2_OFF  67584    // 128 x 17 fp32
#define ZST_OFF  76288    // 128 x 17 fp32
#define AS2_OFF  84992    // 128 x 17 fp32
#define GEMM_SMEM 93696

extern __shared__ unsigned char gsmem[];

__global__ void __launch_bounds__(256, 2) gemm_kernel(
    const float* __restrict__ x,  const float* __restrict__ b1,
    const float* __restrict__ b2, const float* __restrict__ b3,
    float* __restrict__ out)
{
    const int tid  = threadIdx.x;
    const int warp = tid >> 5;
    const int lane = tid & 31;
    const int wm   = warp & 3;
    const int wn   = warp >> 2;
    const int mb   = blockIdx.x >> 4;
    const int nb   = blockIdx.x & 15;
    const int nc   = (nb >> 2) + 1;

    const uint32_t sb = smem_u32(gsmem);

    auto pfA = [&](int kb, int buf) {
        uint32_t dst = sb + ABUF_OFF + (uint32_t)buf * 16384 + (uint32_t)tid * 64;
        const unsigned char* src = (const unsigned char*)g_xh
            + (size_t)(mb * 4 + kb) * 16384 + (size_t)tid * 64;
        #pragma unroll
        for (int i = 0; i < 4; ++i) CP_ASYNC16(dst + i * 16, src + i * 16);
    };
    auto pfB = [&](int kb, int buf) {
        uint32_t dst = sb + BBUF_OFF + (uint32_t)buf * 16384 + (uint32_t)tid * 64;
        const unsigned char* src = (const unsigned char*)g_w1t
            + (size_t)(nb * 16 + kb * 4) * 4096 + (size_t)tid * 64;
        #pragma unroll
        for (int i = 0; i < 4; ++i) CP_ASYNC16(dst + i * 16, src + i * 16);
    };

    pfA(0, 0); pfB(0, 0); CP_COMMIT();
    if (nc > 1) { pfA(1, 1); pfB(1, 1); CP_COMMIT(); }

    float acc[2][8][4];
    #pragma unroll
    for (int mt = 0; mt < 2; ++mt)
        #pragma unroll
        for (int t = 0; t < 8; ++t)
            #pragma unroll
            for (int q = 0; q < 4; ++q) acc[mt][t][q] = 0.f;

    const int arow0 = wm * 32 + (lane & 7) + ((lane >> 3) & 1) * 8;
    const int bk    = (lane & 7) + ((lane >> 3) & 1) * 8;

    for (int kb = 0; kb < nc; ++kb) {
        if (kb < nc - 1) { CP_WAIT1(); } else { CP_WAIT0(); }
        __syncthreads();
        const uint32_t aBuf = sb + ABUF_OFF + (uint32_t)(kb & 1) * 16384;
        const uint32_t bBuf = sb + BBUF_OFF + (uint32_t)(kb & 1) * 16384;
        #pragma unroll
        for (int kt = 0; kt < 4; ++kt) {
            uint32_t af[2][4], bf[4][4];
            uint32_t g = (uint32_t)(2 * kt + (lane >> 4));
            uint32_t offk = ((g ^ (uint32_t)(arow0 & 7)) << 4);
            ldsm4(af[0], aBuf + (uint32_t)arow0 * 128 + offk);
            uint32_t offk1 = ((g ^ (uint32_t)((arow0 + 16) & 7)) << 4);
            ldsm4(af[1], aBuf + (uint32_t)(arow0 + 16) * 128 + offk1);
            #pragma unroll
            for (int p = 0; p < 4; ++p) {
                uint32_t cidx = (uint32_t)(wn * 8 + 2 * p + (lane >> 4));
                ldsm4t(bf[p], bBuf + (uint32_t)kt * 4096 + (uint32_t)bk * 256
                              + ((cidx ^ (uint32_t)(lane & 7)) << 4));
            }
            #pragma unroll
            for (int mt = 0; mt < 2; ++mt)
                #pragma unroll
                for (int p = 0; p < 4; ++p) {
                    mma_f16(acc[mt][2 * p],     af[mt], &bf[p][0]);
                    mma_f16(acc[mt][2 * p + 1], af[mt], &bf[p][2]);
                }
        }
        __syncthreads();
        if (kb + 2 < nc) { pfA(kb + 2, kb & 1); pfB(kb + 2, kb & 1); CP_COMMIT(); }
    }
    // A/B buffers dead now.

    float* xs  = (float*)(gsmem + XS2_OFF);
    float* zst = (float*)(gsmem + ZST_OFF);
    float* as2 = (float*)(gsmem + AS2_OFF);

    // ---- stage h1 = tanh(acc + b1) fp16 into swizzled A-tile format (ABUF) ----
    {
        const int h  = (lane & 3) * 2;
        const int rq = lane >> 2;
        const int r0 = wm * 32 + rq;
        #pragma unroll
        for (int t = 0; t < 8; ++t) {
            int l = nb * 16 + wn * 8 + t;
            float2 b1v = make_float2(0.f, 0.f);
            if (l < LL) b1v = *(const float2*)(b1 + l * 8 + h);
            int lcol = (wn * 8 + t) * 8 + h;
            uint32_t base = (uint32_t)(lcol >> 6) * 16384
                          + (((uint32_t)((lcol & 63) >> 3) ^ (uint32_t)(rq & 7)) << 4)
                          + (uint32_t)((lcol & 7) * 2);
            #pragma unroll
            for (int mt = 0; mt < 2; ++mt) {
                uint32_t a0 = base + (uint32_t)(r0 + mt * 16) * 128;
                *(uint32_t*)(gsmem + a0) =
                    pack_hh(ftanha(acc[mt][t][0] + b1v.x), ftanha(acc[mt][t][1] + b1v.y));
                *(uint32_t*)(gsmem + a0 + 8 * 128) =
                    pack_hh(ftanha(acc[mt][t][2] + b1v.x), ftanha(acc[mt][t][3] + b1v.y));
            }
        }
    }
    // ---- stage x columns nb*16+1 .. nb*16+16 ----
    #pragma unroll
    for (int i = 0; i < 8; ++i) {
        int v = tid + i * 256;
        int r = v >> 4, cc = v & 15;
        int col = nb * 16 + 1 + cc;
        xs[r * 17 + cc] = (col < DD) ? x[(size_t)(mb * 128 + r) * DD + col] : 0.f;
    }

    // ---- pre-barrier loads: W2 fragments + b2 ----
    const int w = warp;
    uint4 bh4 = g_w2f [(nb * 8 + w) * 32 + lane];
    uint4 bl4 = g_w2fl[(nb * 8 + w) * 32 + lane];
    float2 b2v[2];
    #pragma unroll
    for (int nt = 0; nt < 2; ++nt) {
        int l = nb * 16 + 2 * w + nt;
        b2v[nt] = (l < LL) ? *(const float2*)(b2 + l * 8 + (lane & 3) * 2)
                           : make_float2(0.f, 0.f);
    }

    __syncthreads();   // h1a visible

    // ---- MMA2: layer 2 (block-diag, hi/lo split); h2 -> BBUF (A-swizzled fp16) ----
    {
        float acc2[8][2][4];
        #pragma unroll
        for (int mt = 0; mt < 8; ++mt)
            #pragma unroll
            for (int nt = 0; nt < 2; ++nt)
                #pragma unroll
                for (int q = 0; q < 4; ++q) acc2[mt][nt][q] = 0.f;

        const int ar = (lane & 7) + ((lane >> 3) & 1) * 8;
        const uint32_t gg = (uint32_t)(2 * (w & 3) + (lane >> 4));
        const uint32_t ck = (uint32_t)(w >> 2) * 16384;
        #pragma unroll
        for (int mt = 0; mt < 8; ++mt) {
            uint32_t af[4];
            uint32_t row = (uint32_t)(mt * 16 + ar);
            ldsm4(af, sb + ck + row * 128 + ((gg ^ (row & 7)) << 4));
            mma_f16(acc2[mt][0], af, (const uint32_t*)&bh4);
            mma_f16(acc2[mt][0], af, (const uint32_t*)&bl4);
            mma_f16(acc2[mt][1], af, ((const uint32_t*)&bh4) + 2);
            mma_f16(acc2[mt][1], af, ((const uint32_t*)&bl4) + 2);
        }
        // h2 = tanh(acc2 + b2) -> BBUF in A-swizzled format
        const int rq = lane >> 2;
        #pragma unroll
        for (int mt = 0; mt < 8; ++mt) {
            int r = mt * 16 + rq;
            #pragma unroll
            for (int nt = 0; nt < 2; ++nt) {
                int lcol = w * 16 + nt * 8 + (lane & 3) * 2;
                uint32_t base = BBUF_OFF + (uint32_t)(lcol >> 6) * 16384
                              + (uint32_t)((lcol & 7) * 2);
                uint32_t swa = base + (uint32_t)r * 128
                             + (((uint32_t)((lcol & 63) >> 3) ^ (uint32_t)(r & 7)) << 4);
                *(uint32_t*)(gsmem + swa) =
                    pack_hh(ftanha(acc2[mt][nt][0] + b2v[nt].x),
                            ftanha(acc2[mt][nt][1] + b2v[nt].y));
                uint32_t swb = base + (uint32_t)(r + 8) * 128
                             + (((uint32_t)((lcol & 63) >> 3) ^ (uint32_t)((r + 8) & 7)) << 4);
                *(uint32_t*)(gsmem + swb) =
                    pack_hh(ftanha(acc2[mt][nt][2] + b2v[nt].x),
                            ftanha(acc2[mt][nt][3] + b2v[nt].y));
            }
        }
    }

    // ---- load W3 fragments + b3 (latency hidden by barrier) ----
    uint4 w3f[8];
    #pragma unroll
    for (int kt = 0; kt < 8; ++kt)
        w3f[kt] = g_w3f[(nb * 8 + kt) * 32 + lane];
    float2 b3v[4];
    #pragma unroll
    for (int nt = 0; nt < 4; ++nt) {
        int l = nb * 16 + 4 * nt + (lane & 3);
        b3v[nt] = (l < LL) ? *(const float2*)(b3 + l * 2) : make_float2(0.f, 0.f);
    }

    __syncthreads();   // h2a visible

    // ---- MMA3: layer 3 block-diag; warp w owns m-tile w (rows w*16..+15) ----
    {
        float acc3[4][4];
        #pragma unroll
        for (int nt = 0; nt < 4; ++nt)
            #pragma unroll
            for (int q = 0; q < 4; ++q) acc3[nt][q] = 0.f;

        const int ar3 = (lane & 7) + ((lane >> 3) & 1) * 8;
        #pragma unroll
        for (int kt = 0; kt < 8; ++kt) {
            uint32_t g = (uint32_t)(2 * kt + (lane >> 4));
            uint32_t row = (uint32_t)(w * 16 + ar3);
            uint32_t addr = sb + BBUF_OFF + (g >> 3) * 16384 + row * 128
                          + (((g & 7) ^ (row & 7)) << 4);
            uint32_t af[4];
            ldsm4(af, addr);
            mma_f16(acc3[kt >> 1], af, (const uint32_t*)&w3f[kt]);       // hi
            mma_f16(acc3[kt >> 1], af, ((const uint32_t*)&w3f[kt]) + 2); // lo
        }

        // ---- z from fragments: thread owns (mu,al) for jl=4nt+(lane&3), 2 rows ----
        const int rq3 = lane >> 2;
        #pragma unroll
        for (int nt = 0; nt < 4; ++nt) {
            int jl = 4 * nt + (lane & 3);
            int r1 = w * 16 + rq3;
            int r2 = r1 + 8;
            float mu1 = acc3[nt][0] + b3v[nt].x;
            float al1 = acc3[nt][1] + b3v[nt].y;
            float mu2 = acc3[nt][2] + b3v[nt].x;
            float al2 = acc3[nt][3] + b3v[nt].y;
            zst[r1 * 17 + jl] = (xs[r1 * 17 + jl] - mu1) * __expf(-al1);
            as2[r1 * 17 + jl] = al1;
            zst[r2 * 17 + jl] = (xs[r2 * 17 + jl] - mu2) * __expf(-al2);
            as2[r2 * 17 + jl] = al2;
        }
    }
    __syncthreads();

    // ---- flush z (coalesced, reversed) + alpha partial ----
    #pragma unroll
    for (int it = 0; it < 8; ++it) {
        int v = tid + it * 256;
        int r = v >> 4, cc = v & 15;
        int col = 239 - nb * 16 + cc;
        if (col >= 0)
            out[(size_t)(mb * 128 + r) * DD + col] = zst[r * 17 + (15 - cc)];
    }
    if (tid < 128) {
        float s = 0.f;
        #pragma unroll
        for (int q = 0; q < 16; ++q) s += as2[tid * 17 + q];
        g_apart[nb * BB + mb * 128 + tid] = s;
    }
}

// ============== final: col 255 + log_det ==============
__global__ void __launch_bounds__(128) zfinal_kernel(
    const float* __restrict__ x, const float* __restrict__ ipar,
    float* __restrict__ out, int out_size)
{
    int r = blockIdx.x * 128 + threadIdx.x;
    float s = 0.f;
    #pragma unroll
    for (int nb = 0; nb < 16; ++nb) s += g_apart[nb * BB + r];
    float ip0 = ipar[0], ip1 = ipar[1];
    out[(size_t)r * DD + 255] = (x[(size_t)r * DD] - ip0) * __expf(-ip1);
    if (out_size > BB * DD)
        out[(size_t)BB * DD + r] = -(ip1 + s);
}

extern "C" void kernel_launch(void* const* d_in, const int* in_sizes, int n_in,
                              void* d_out, int out_size)
{
    const float* x    = (const float*)d_in[0];
    const float* ipar = (const float*)d_in[1];
    const float* W1   = (const float*)d_in[2];
    const float* b1   = (const float*)d_in[3];
    const float* W2   = (const float*)d_in[4];
    const float* b2   = (const float*)d_in[5];
    const float* W3   = (const float*)d_in[6];
    const float* b3   = (const float*)d_in[7];
    float* out = (float*)d_out;

    prep_kernel<<<2336, 256>>>(W1, x, W2, W3);
    cudaFuncSetAttribute(gemm_kernel, cudaFuncAttributeMaxDynamicSharedMemorySize, GEMM_SMEM);
    gemm_kernel<<<2048, 256, GEMM_SMEM>>>(x, b1, b2, b3, out);
    zfinal_kernel<<<BB / 128, 128>>>(x, ipar, out, out_size);
}